// round 8
// baseline (speedup 1.0000x reference)
#include <cuda_runtime.h>
#include <cuda_fp16.h>
#include <cuda_bf16.h>
#include <cstdint>

// ---------------- problem constants ----------------
namespace {
constexpr int NN   = 100000;
constexpr int NE   = 1600000;
constexpr int NH   = 4;
constexpr int DD   = 64;
constexpr int CIN  = 128;
constexpr int CTOT = 256;
constexpr float NEG_SLOPE = 0.2f;
constexpr float BN_EPS    = 1e-5f;
constexpr int SCAN_B = (NN + 1023) / 1024;
}

// ---------------- scratch ----------------
__device__ __align__(16) __half g_h  [(size_t)NN * CTOT];   // projected feats (fp16)
__device__ __align__(16) float  g_res[(size_t)NN * CTOT];   // residual proj
__device__ __align__(16) float  g_el [NN * NH];
__device__ __align__(16) float  g_er [NN * NH];
__device__ int                  g_cnt[NN];
__device__ int                  g_off[NN + 1];
__device__ int                  g_cur[NN];
__device__ int                  g_ssrc[NE];                 // src sorted by dst
__device__ uint2                g_sexh[NE];                 // ex (4 x fp16) sorted by dst
__device__ float                g_bnsum[DD];
__device__ float                g_bnss [DD];
__device__ int                  g_bsum[128];

// ---------------- helpers ----------------
__device__ __forceinline__ void mma_bf16(float* c, const uint32_t* a,
                                         uint32_t b0, uint32_t b1) {
    asm volatile(
        "mma.sync.aligned.m16n8k16.row.col.f32.bf16.bf16.f32 "
        "{%0,%1,%2,%3},{%4,%5,%6,%7},{%8,%9},{%0,%1,%2,%3};"
        : "+f"(c[0]), "+f"(c[1]), "+f"(c[2]), "+f"(c[3])
        : "r"(a[0]), "r"(a[1]), "r"(a[2]), "r"(a[3]), "r"(b0), "r"(b1));
}
__device__ __forceinline__ void split_pack(float x, float y,
                                           uint32_t& hi, uint32_t& lo) {
    __nv_bfloat16 hx = __float2bfloat16(x);
    __nv_bfloat16 hy = __float2bfloat16(y);
    __nv_bfloat16 lx = __float2bfloat16(x - __bfloat162float(hx));
    __nv_bfloat16 ly = __float2bfloat16(y - __bfloat162float(hy));
    __nv_bfloat162 h2 = __nv_bfloat162(hx, hy);
    __nv_bfloat162 l2 = __nv_bfloat162(lx, ly);
    hi = *(uint32_t*)&h2;
    lo = *(uint32_t*)&l2;
}
__device__ __forceinline__ float elu1(float v) {
    return v > 0.f ? v : (__expf(v) - 1.f);
}

// ---------------- kernels ----------------

__global__ void zero_kernel() {
    int i = blockIdx.x * blockDim.x + threadIdx.x;
    if (i < NN) g_cnt[i] = 0;
    if (i < DD) { g_bnsum[i] = 0.f; g_bnss[i] = 0.f; }
}

// bf16x3 split tensor-core GEMM + fused el/er epilogue.
// Block 128x128, BK=32, 8 warps (4m x 2n), warp tile 32x64 (= one head wide).
__global__ __launch_bounds__(256) void gemm_bf16_kernel(
        const float* __restrict__ feats,
        const float* __restrict__ fcw,
        const float* __restrict__ resw,
        const float* __restrict__ al,
        const float* __restrict__ ar) {
    __shared__ uint32_t AsHi[128][20], AsLo[128][20];
    __shared__ uint32_t BsHi[128][20], BsLo[128][20];

    const int tid  = threadIdx.x;
    const int lane = tid & 31;
    const int w    = tid >> 5;
    const int wm   = w & 3;
    const int wn   = w >> 2;
    const int rb   = blockIdx.y * 128;
    const int cb   = blockIdx.x * 128;

    float c[2][8][4];
#pragma unroll
    for (int mt = 0; mt < 2; ++mt)
#pragma unroll
        for (int nt = 0; nt < 8; ++nt)
#pragma unroll
            for (int q = 0; q < 4; ++q) c[mt][nt][q] = 0.f;

    const int qrow = lane >> 2;
    const int qcol = lane & 3;

    float4 ra[4], rbv[4];
    {
#pragma unroll
        for (int it = 0; it < 4; ++it) {
            int i   = it * 256 + tid;
            int row = i >> 3;
            int kq  = (i & 7) * 4;
            int gr  = rb + row;
            ra[it] = make_float4(0.f, 0.f, 0.f, 0.f);
            if (gr < NN) ra[it] = *(const float4*)&feats[(size_t)gr * CIN + kq];
        }
#pragma unroll
        for (int it = 0; it < 4; ++it) {
            int i   = it * 256 + tid;
            int col = i >> 3;
            int kq  = (i & 7) * 4;
            int gc  = cb + col;
            const float* wp = (gc < CTOT) ? &fcw[(size_t)gc * CIN]
                                          : &resw[(size_t)(gc - CTOT) * CIN];
            rbv[it] = *(const float4*)&wp[kq];
        }
    }

#pragma unroll
    for (int chunk = 0; chunk < 4; ++chunk) {
#pragma unroll
        for (int it = 0; it < 4; ++it) {
            int i   = it * 256 + tid;
            int row = i >> 3;
            int kq  = (i & 7) * 4;
            uint32_t h0, l0, h1, l1;
            split_pack(ra[it].x, ra[it].y, h0, l0);
            split_pack(ra[it].z, ra[it].w, h1, l1);
            AsHi[row][kq / 2]     = h0; AsLo[row][kq / 2]     = l0;
            AsHi[row][kq / 2 + 1] = h1; AsLo[row][kq / 2 + 1] = l1;
            split_pack(rbv[it].x, rbv[it].y, h0, l0);
            split_pack(rbv[it].z, rbv[it].w, h1, l1);
            BsHi[row][kq / 2]     = h0; BsLo[row][kq / 2]     = l0;
            BsHi[row][kq / 2 + 1] = h1; BsLo[row][kq / 2 + 1] = l1;
        }
        __syncthreads();

        if (chunk < 3) {
            const int ks = (chunk + 1) * 32;
#pragma unroll
            for (int it = 0; it < 4; ++it) {
                int i   = it * 256 + tid;
                int row = i >> 3;
                int kq  = (i & 7) * 4;
                int gr  = rb + row;
                ra[it] = make_float4(0.f, 0.f, 0.f, 0.f);
                if (gr < NN) ra[it] = *(const float4*)&feats[(size_t)gr * CIN + ks + kq];
            }
#pragma unroll
            for (int it = 0; it < 4; ++it) {
                int i   = it * 256 + tid;
                int col = i >> 3;
                int kq  = (i & 7) * 4;
                int gc  = cb + col;
                const float* wp = (gc < CTOT) ? &fcw[(size_t)gc * CIN]
                                              : &resw[(size_t)(gc - CTOT) * CIN];
                rbv[it] = *(const float4*)&wp[ks + kq];
            }
        }

#pragma unroll
        for (int k2b = 0; k2b < 16; k2b += 8) {
            uint32_t aH[2][4], aL[2][4];
#pragma unroll
            for (int mt = 0; mt < 2; ++mt) {
                int rw = wm * 32 + mt * 16 + qrow;
                aH[mt][0] = AsHi[rw][k2b + qcol];
                aH[mt][1] = AsHi[rw + 8][k2b + qcol];
                aH[mt][2] = AsHi[rw][k2b + qcol + 4];
                aH[mt][3] = AsHi[rw + 8][k2b + qcol + 4];
                aL[mt][0] = AsLo[rw][k2b + qcol];
                aL[mt][1] = AsLo[rw + 8][k2b + qcol];
                aL[mt][2] = AsLo[rw][k2b + qcol + 4];
                aL[mt][3] = AsLo[rw + 8][k2b + qcol + 4];
            }
#pragma unroll
            for (int nt = 0; nt < 8; ++nt) {
                int cl = wn * 64 + nt * 8 + qrow;
                uint32_t bH0 = BsHi[cl][k2b + qcol];
                uint32_t bH1 = BsHi[cl][k2b + qcol + 4];
                uint32_t bL0 = BsLo[cl][k2b + qcol];
                uint32_t bL1 = BsLo[cl][k2b + qcol + 4];
#pragma unroll
                for (int mt = 0; mt < 2; ++mt) {
                    mma_bf16(c[mt][nt], aH[mt], bH0, bH1);
                    mma_bf16(c[mt][nt], aH[mt], bL0, bL1);
                    mma_bf16(c[mt][nt], aL[mt], bH0, bH1);
                }
            }
        }
        __syncthreads();
    }

    // epilogue: h -> fp16, res -> fp32
#pragma unroll
    for (int mt = 0; mt < 2; ++mt) {
        int r = rb + wm * 32 + mt * 16 + qrow;
#pragma unroll
        for (int nt = 0; nt < 8; ++nt) {
            int cg = cb + wn * 64 + nt * 8 + qcol * 2;
            if (cg < CTOT) {
                if (r < NN)
                    *(__half2*)&g_h[(size_t)r * CTOT + cg] =
                        __floats2half2_rn(c[mt][nt][0], c[mt][nt][1]);
                if (r + 8 < NN)
                    *(__half2*)&g_h[(size_t)(r + 8) * CTOT + cg] =
                        __floats2half2_rn(c[mt][nt][2], c[mt][nt][3]);
            } else {
                int cc = cg - CTOT;
                if (r < NN)
                    *(float2*)&g_res[(size_t)r * CTOT + cc] =
                        make_float2(c[mt][nt][0], c[mt][nt][1]);
                if (r + 8 < NN)
                    *(float2*)&g_res[(size_t)(r + 8) * CTOT + cc] =
                        make_float2(c[mt][nt][2], c[mt][nt][3]);
            }
        }
    }

    // fused el/er: warp tile = exactly one head (64 cols); dot with attn + 4-lane reduce
    if (cb < CTOT) {
        const int head = (cb >> 6) + wn;
#pragma unroll
        for (int mt = 0; mt < 2; ++mt) {
            float pl0 = 0.f, pr0 = 0.f, pl8 = 0.f, pr8 = 0.f;
#pragma unroll
            for (int nt = 0; nt < 8; ++nt) {
                int cg = cb + wn * 64 + nt * 8 + qcol * 2;
                float a0 = al[cg], a1 = al[cg + 1];
                float r0 = ar[cg], r1 = ar[cg + 1];
                pl0 += c[mt][nt][0] * a0 + c[mt][nt][1] * a1;
                pr0 += c[mt][nt][0] * r0 + c[mt][nt][1] * r1;
                pl8 += c[mt][nt][2] * a0 + c[mt][nt][3] * a1;
                pr8 += c[mt][nt][2] * r0 + c[mt][nt][3] * r1;
            }
#pragma unroll
            for (int o = 1; o <= 2; o <<= 1) {
                pl0 += __shfl_xor_sync(0xffffffffu, pl0, o);
                pr0 += __shfl_xor_sync(0xffffffffu, pr0, o);
                pl8 += __shfl_xor_sync(0xffffffffu, pl8, o);
                pr8 += __shfl_xor_sync(0xffffffffu, pr8, o);
            }
            if (qcol == 0) {
                int r = rb + wm * 32 + mt * 16 + qrow;
                if (r < NN)     { g_el[r * NH + head] = pl0; g_er[r * NH + head] = pr0; }
                if (r + 8 < NN) { g_el[(r + 8) * NH + head] = pl8; g_er[(r + 8) * NH + head] = pr8; }
            }
        }
    }
}

// dst histogram (int4-vectorized)
__global__ void hist_kernel(const int* __restrict__ dst) {
    int i = blockIdx.x * blockDim.x + threadIdx.x;
    int i4 = i * 4;
    if (i4 + 3 < NE) {
        int4 d = *(const int4*)&dst[i4];
        atomicAdd(&g_cnt[d.x], 1);
        atomicAdd(&g_cnt[d.y], 1);
        atomicAdd(&g_cnt[d.z], 1);
        atomicAdd(&g_cnt[d.w], 1);
    } else {
        for (int j = i4; j < NE; ++j) atomicAdd(&g_cnt[dst[j]], 1);
    }
}

// 3-kernel exclusive scan of g_cnt -> g_off (+ g_cur copy)
__global__ void scan1_kernel() {
    __shared__ int sd[1024];
    int t = threadIdx.x;
    int gid = blockIdx.x * 1024 + t;
    int v = (gid < NN) ? g_cnt[gid] : 0;
    sd[t] = v; __syncthreads();
    for (int o = 1; o < 1024; o <<= 1) {
        int x = (t >= o) ? sd[t - o] : 0;
        __syncthreads();
        sd[t] += x;
        __syncthreads();
    }
    if (gid < NN) g_off[gid] = sd[t] - v;
    if (t == 1023) g_bsum[blockIdx.x] = sd[1023];
}
__global__ void scan2_kernel() {
    __shared__ int sd[128];
    int t = threadIdx.x;
    int v = (t < SCAN_B) ? g_bsum[t] : 0;
    sd[t] = v; __syncthreads();
    for (int o = 1; o < 128; o <<= 1) {
        int x = (t >= o) ? sd[t - o] : 0;
        __syncthreads();
        sd[t] += x;
        __syncthreads();
    }
    if (t < SCAN_B) g_bsum[t] = sd[t] - v;
}
__global__ void scan3_kernel() {
    int gid = blockIdx.x * 1024 + threadIdx.x;
    if (gid < NN) {
        int o = g_off[gid] + g_bsum[blockIdx.x];
        g_off[gid] = o;
        g_cur[gid] = o;
    }
    if (gid == 0) g_off[NN] = NE;
}

// edge pass: ex = exp(lrelu(el+er)) -> fp16, counting-sort by dst.
__global__ void scatter_kernel(const int* __restrict__ src,
                               const int* __restrict__ dst) {
    int i = blockIdx.x * blockDim.x + threadIdx.x;
    if (i >= NE) return;
    int s = src[i], d = dst[i];
    float4 a = *(const float4*)&g_el[s * NH];
    float4 b = *(const float4*)&g_er[d * NH];
    float t;
    t = a.x + b.x; t = t > 0.f ? t : NEG_SLOPE * t; __half e0 = __float2half(__expf(t));
    t = a.y + b.y; t = t > 0.f ? t : NEG_SLOPE * t; __half e1 = __float2half(__expf(t));
    t = a.z + b.z; t = t > 0.f ? t : NEG_SLOPE * t; __half e2 = __float2half(__expf(t));
    t = a.w + b.w; t = t > 0.f ? t : NEG_SLOPE * t; __half e3 = __float2half(__expf(t));
    int p = atomicAdd(&g_cur[d], 1);
    __half2 p01 = __halves2half2(e0, e1);
    __half2 p23 = __halves2half2(e2, e3);
    g_ssrc[p] = s;
    g_sexh[p] = make_uint2(*(uint32_t*)&p01, *(uint32_t*)&p23);
}

// aggregation + in-register denom + residual + bias + ELU + mean + BN partials.
// One warp/node; thread: 2 heads x 4 d-elems; edge loop unrolled x4.
__global__ __launch_bounds__(256) void agg_kernel(const float* __restrict__ bias,
                                                  float* __restrict__ out) {
    __shared__ float sSum[DD], sSS[DD];
    if (threadIdx.x < DD) { sSum[threadIdx.x] = 0.f; sSS[threadIdx.x] = 0.f; }
    __syncthreads();

    int node = blockIdx.x * 8 + (threadIdx.x >> 5);   // NN % 8 == 0: all valid
    int lane = threadIdx.x & 31;
    int grp = lane >> 4;
    int idx = lane & 15;
    int offA = grp * 64 + idx * 4;
    int offB = (grp + 2) * 64 + idx * 4;
    int beg = g_off[node], end = g_off[node + 1];

    float4 accA = make_float4(0.f, 0.f, 0.f, 0.f);
    float4 accB = make_float4(0.f, 0.f, 0.f, 0.f);
    float sA = 0.f, sB = 0.f;

    int e = beg;
#pragma unroll 1
    for (; e + 3 < end; e += 4) {
        int s0 = g_ssrc[e], s1 = g_ssrc[e + 1], s2 = g_ssrc[e + 2], s3 = g_ssrc[e + 3];
        uint2 w0 = g_sexh[e], w1 = g_sexh[e + 1], w2 = g_sexh[e + 2], w3 = g_sexh[e + 3];
        uint2 ra0 = *(const uint2*)&g_h[(size_t)s0 * CTOT + offA];
        uint2 rb0 = *(const uint2*)&g_h[(size_t)s0 * CTOT + offB];
        uint2 ra1 = *(const uint2*)&g_h[(size_t)s1 * CTOT + offA];
        uint2 rb1 = *(const uint2*)&g_h[(size_t)s1 * CTOT + offB];
        uint2 ra2 = *(const uint2*)&g_h[(size_t)s2 * CTOT + offA];
        uint2 rb2 = *(const uint2*)&g_h[(size_t)s2 * CTOT + offB];
        uint2 ra3 = *(const uint2*)&g_h[(size_t)s3 * CTOT + offA];
        uint2 rb3 = *(const uint2*)&g_h[(size_t)s3 * CTOT + offB];
        float wA0 = grp ? __high2float(*(__half2*)&w0.x) : __low2float(*(__half2*)&w0.x);
        float wB0 = grp ? __high2float(*(__half2*)&w0.y) : __low2float(*(__half2*)&w0.y);
        float wA1 = grp ? __high2float(*(__half2*)&w1.x) : __low2float(*(__half2*)&w1.x);
        float wB1 = grp ? __high2float(*(__half2*)&w1.y) : __low2float(*(__half2*)&w1.y);
        float wA2 = grp ? __high2float(*(__half2*)&w2.x) : __low2float(*(__half2*)&w2.x);
        float wB2 = grp ? __high2float(*(__half2*)&w2.y) : __low2float(*(__half2*)&w2.y);
        float wA3 = grp ? __high2float(*(__half2*)&w3.x) : __low2float(*(__half2*)&w3.x);
        float wB3 = grp ? __high2float(*(__half2*)&w3.y) : __low2float(*(__half2*)&w3.y);
        sA += (wA0 + wA1) + (wA2 + wA3);
        sB += (wB0 + wB1) + (wB2 + wB3);
        float2 t0, t1;
        t0 = __half22float2(*(__half2*)&ra0.x); accA.x += wA0 * t0.x; accA.y += wA0 * t0.y;
        t1 = __half22float2(*(__half2*)&ra0.y); accA.z += wA0 * t1.x; accA.w += wA0 * t1.y;
        t0 = __half22float2(*(__half2*)&rb0.x); accB.x += wB0 * t0.x; accB.y += wB0 * t0.y;
        t1 = __half22float2(*(__half2*)&rb0.y); accB.z += wB0 * t1.x; accB.w += wB0 * t1.y;
        t0 = __half22float2(*(__half2*)&ra1.x); accA.x += wA1 * t0.x; accA.y += wA1 * t0.y;
        t1 = __half22float2(*(__half2*)&ra1.y); accA.z += wA1 * t1.x; accA.w += wA1 * t1.y;
        t0 = __half22float2(*(__half2*)&rb1.x); accB.x += wB1 * t0.x; accB.y += wB1 * t0.y;
        t1 = __half22float2(*(__half2*)&rb1.y); accB.z += wB1 * t1.x; accB.w += wB1 * t1.y;
        t0 = __half22float2(*(__half2*)&ra2.x); accA.x += wA2 * t0.x; accA.y += wA2 * t0.y;
        t1 = __half22float2(*(__half2*)&ra2.y); accA.z += wA2 * t1.x; accA.w += wA2 * t1.y;
        t0 = __half22float2(*(__half2*)&rb2.x); accB.x += wB2 * t0.x; accB.y += wB2 * t0.y;
        t1 = __half22float2(*(__half2*)&rb2.y); accB.z += wB2 * t1.x; accB.w += wB2 * t1.y;
        t0 = __half22float2(*(__half2*)&ra3.x); accA.x += wA3 * t0.x; accA.y += wA3 * t0.y;
        t1 = __half22float2(*(__half2*)&ra3.y); accA.z += wA3 * t1.x; accA.w += wA3 * t1.y;
        t0 = __half22float2(*(__half2*)&rb3.x); accB.x += wB3 * t0.x; accB.y += wB3 * t0.y;
        t1 = __half22float2(*(__half2*)&rb3.y); accB.z += wB3 * t1.x; accB.w += wB3 * t1.y;
    }
#pragma unroll 1
    for (; e < end; ++e) {
        int s0 = g_ssrc[e];
        uint2 w0 = g_sexh[e];
        uint2 ra0 = *(const uint2*)&g_h[(size_t)s0 * CTOT + offA];
        uint2 rb0 = *(const uint2*)&g_h[(size_t)s0 * CTOT + offB];
        float wA0 = grp ? __high2float(*(__half2*)&w0.x) : __low2float(*(__half2*)&w0.x);
        float wB0 = grp ? __high2float(*(__half2*)&w0.y) : __low2float(*(__half2*)&w0.y);
        sA += wA0; sB += wB0;
        float2 t0, t1;
        t0 = __half22float2(*(__half2*)&ra0.x); accA.x += wA0 * t0.x; accA.y += wA0 * t0.y;
        t1 = __half22float2(*(__half2*)&ra0.y); accA.z += wA0 * t1.x; accA.w += wA0 * t1.y;
        t0 = __half22float2(*(__half2*)&rb0.x); accB.x += wB0 * t0.x; accB.y += wB0 * t0.y;
        t1 = __half22float2(*(__half2*)&rb0.y); accB.z += wB0 * t1.x; accB.w += wB0 * t1.y;
    }

    float invA = (sA > 0.f) ? 1.f / sA : 0.f;
    float invB = (sB > 0.f) ? 1.f / sB : 0.f;
    const float* rp = &g_res[(size_t)node * CTOT];
    float4 rA = *(const float4*)&rp[offA];
    float4 rB = *(const float4*)&rp[offB];
    float4 bA = *(const float4*)&bias[offA];
    float4 bB = *(const float4*)&bias[offB];
    float4 tot;
    tot.x = elu1(accA.x * invA + rA.x + bA.x) + elu1(accB.x * invB + rB.x + bB.x);
    tot.y = elu1(accA.y * invA + rA.y + bA.y) + elu1(accB.y * invB + rB.y + bB.y);
    tot.z = elu1(accA.z * invA + rA.z + bA.z) + elu1(accB.z * invB + rB.z + bB.z);
    tot.w = elu1(accA.w * invA + rA.w + bA.w) + elu1(accB.w * invB + rB.w + bB.w);
    tot.x += __shfl_xor_sync(0xffffffffu, tot.x, 16);
    tot.y += __shfl_xor_sync(0xffffffffu, tot.y, 16);
    tot.z += __shfl_xor_sync(0xffffffffu, tot.z, 16);
    tot.w += __shfl_xor_sync(0xffffffffu, tot.w, 16);
    if (grp == 0) {
        float4 o = make_float4(tot.x * 0.25f, tot.y * 0.25f,
                               tot.z * 0.25f, tot.w * 0.25f);
        *(float4*)&out[(size_t)node * DD + idx * 4] = o;
        int d0 = idx * 4;
        atomicAdd(&sSum[d0 + 0], o.x); atomicAdd(&sSS[d0 + 0], o.x * o.x);
        atomicAdd(&sSum[d0 + 1], o.y); atomicAdd(&sSS[d0 + 1], o.y * o.y);
        atomicAdd(&sSum[d0 + 2], o.z); atomicAdd(&sSS[d0 + 2], o.z * o.z);
        atomicAdd(&sSum[d0 + 3], o.w); atomicAdd(&sSS[d0 + 3], o.w * o.w);
    }
    __syncthreads();
    if (threadIdx.x < DD) {
        atomicAdd(&g_bnsum[threadIdx.x], sSum[threadIdx.x]);
        atomicAdd(&g_bnss[threadIdx.x],  sSS[threadIdx.x]);
    }
}

__global__ void bnapply_kernel(float* __restrict__ out,
                               const float* __restrict__ gamma,
                               const float* __restrict__ beta) {
    int gid = blockIdx.x * blockDim.x + threadIdx.x;
    if (gid >= NN * DD) return;
    int d = gid & 63;
    const float invn = 1.f / (float)NN;
    float mu  = g_bnsum[d] * invn;
    float var = g_bnss[d] * invn - mu * mu;
    out[gid] = (out[gid] - mu) * rsqrtf(var + BN_EPS) * gamma[d] + beta[d];
}

// ---------------- launch ----------------
extern "C" void kernel_launch(void* const* d_in, const int* in_sizes, int n_in,
                              void* d_out, int out_size) {
    const float* feats = (const float*)d_in[0];
    const int*   src   = (const int*)d_in[1];
    const int*   dst   = (const int*)d_in[2];
    const float* fcw   = (const float*)d_in[3];
    const float* al    = (const float*)d_in[4];
    const float* ar    = (const float*)d_in[5];
    const float* resw  = (const float*)d_in[6];
    const float* bias  = (const float*)d_in[7];
    const float* gamma = (const float*)d_in[8];
    const float* beta  = (const float*)d_in[9];
    float* out = (float*)d_out;

    zero_kernel<<<(NN + 255) / 256, 256>>>();
    gemm_bf16_kernel<<<dim3(4, (NN + 127) / 128), 256>>>(feats, fcw, resw, al, ar);
    hist_kernel<<<(NE / 4 + 255) / 256, 256>>>(dst);
    scan1_kernel<<<SCAN_B, 1024>>>();
    scan2_kernel<<<1, 128>>>();
    scan3_kernel<<<SCAN_B, 1024>>>();
    scatter_kernel<<<(NE + 255) / 256, 256>>>(src, dst);
    agg_kernel<<<NN / 8, 256>>>(bias, out);
    bnapply_kernel<<<(NN * DD + 255) / 256, 256>>>(out, gamma, beta);
}

// round 9
// speedup vs baseline: 1.0506x; 1.0506x over previous
#include <cuda_runtime.h>
#include <cuda_fp16.h>
#include <cuda_bf16.h>
#include <cstdint>

// ---------------- problem constants ----------------
namespace {
constexpr int NN   = 100000;
constexpr int NE   = 1600000;
constexpr int NH   = 4;
constexpr int DD   = 64;
constexpr int CIN  = 128;
constexpr int CTOT = 256;
constexpr float NEG_SLOPE = 0.2f;
constexpr float BN_EPS    = 1e-5f;
constexpr int SCAN_B = (NN + 1023) / 1024;
}

// ---------------- scratch ----------------
__device__ __align__(16) __half g_h  [(size_t)NN * CTOT];   // projected feats (fp16)
__device__ __align__(16) float  g_res[(size_t)NN * CTOT];   // residual proj
__device__ __align__(16) float  g_el [NN * NH];
__device__ __align__(16) float  g_er [NN * NH];
__device__ int                  g_cnt[NN];
__device__ int                  g_off[NN + 1];
__device__ int                  g_cur[NN];
__device__ int                  g_ssrc[NE];                 // src sorted by dst
__device__ uint2                g_sexh[NE];                 // ex (4 x fp16) sorted by dst
__device__ float                g_bnsum[DD];
__device__ float                g_bnss [DD];
__device__ int                  g_bsum[128];

// ---------------- helpers ----------------
__device__ __forceinline__ void mma_bf16(float* c, const uint32_t* a,
                                         uint32_t b0, uint32_t b1) {
    asm volatile(
        "mma.sync.aligned.m16n8k16.row.col.f32.bf16.bf16.f32 "
        "{%0,%1,%2,%3},{%4,%5,%6,%7},{%8,%9},{%0,%1,%2,%3};"
        : "+f"(c[0]), "+f"(c[1]), "+f"(c[2]), "+f"(c[3])
        : "r"(a[0]), "r"(a[1]), "r"(a[2]), "r"(a[3]), "r"(b0), "r"(b1));
}
__device__ __forceinline__ void split_pack(float x, float y,
                                           uint32_t& hi, uint32_t& lo) {
    __nv_bfloat16 hx = __float2bfloat16(x);
    __nv_bfloat16 hy = __float2bfloat16(y);
    __nv_bfloat16 lx = __float2bfloat16(x - __bfloat162float(hx));
    __nv_bfloat16 ly = __float2bfloat16(y - __bfloat162float(hy));
    __nv_bfloat162 h2 = __nv_bfloat162(hx, hy);
    __nv_bfloat162 l2 = __nv_bfloat162(lx, ly);
    hi = *(uint32_t*)&h2;
    lo = *(uint32_t*)&l2;
}
__device__ __forceinline__ float elu1(float v) {
    return v > 0.f ? v : (__expf(v) - 1.f);
}
// k2-column interleave: within each 8-block, (q, q+4) -> (2q, 2q+1)
// so fragment pairs ([k],[k+4]) are adjacent -> LDS.64 loads.
__device__ __forceinline__ int nc_map(int k2) {
    return (k2 & 8) | (((k2 & 3) << 1) | ((k2 >> 2) & 1));
}

// ---------------- kernels ----------------

__global__ void zero_kernel() {
    int i = blockIdx.x * blockDim.x + threadIdx.x;
    if (i < NN) g_cnt[i] = 0;
    if (i < DD) { g_bnsum[i] = 0.f; g_bnss[i] = 0.f; }
}

// bf16x3 split tensor-core GEMM + fused el/er epilogue.
// Block 128x128, BK=32, 8 warps (4m x 2n), warp tile 32x64 (= one head wide).
__global__ __launch_bounds__(256) void gemm_bf16_kernel(
        const float* __restrict__ feats,
        const float* __restrict__ fcw,
        const float* __restrict__ resw,
        const float* __restrict__ al,
        const float* __restrict__ ar) {
    __shared__ __align__(16) uint32_t AsHi[128][20], AsLo[128][20];
    __shared__ __align__(16) uint32_t BsHi[128][20], BsLo[128][20];

    const int tid  = threadIdx.x;
    const int lane = tid & 31;
    const int w    = tid >> 5;
    const int wm   = w & 3;
    const int wn   = w >> 2;
    const int rb   = blockIdx.y * 128;
    const int cb   = blockIdx.x * 128;

    float c[2][8][4];
#pragma unroll
    for (int mt = 0; mt < 2; ++mt)
#pragma unroll
        for (int nt = 0; nt < 8; ++nt)
#pragma unroll
            for (int q = 0; q < 4; ++q) c[mt][nt][q] = 0.f;

    const int qrow = lane >> 2;
    const int qcol = lane & 3;

    float4 ra[4], rbv[4];
    {
#pragma unroll
        for (int it = 0; it < 4; ++it) {
            int i   = it * 256 + tid;
            int row = i >> 3;
            int kq  = (i & 7) * 4;
            int gr  = rb + row;
            ra[it] = make_float4(0.f, 0.f, 0.f, 0.f);
            if (gr < NN) ra[it] = *(const float4*)&feats[(size_t)gr * CIN + kq];
        }
#pragma unroll
        for (int it = 0; it < 4; ++it) {
            int i   = it * 256 + tid;
            int col = i >> 3;
            int kq  = (i & 7) * 4;
            int gc  = cb + col;
            const float* wp = (gc < CTOT) ? &fcw[(size_t)gc * CIN]
                                          : &resw[(size_t)(gc - CTOT) * CIN];
            rbv[it] = *(const float4*)&wp[kq];
        }
    }

#pragma unroll
    for (int chunk = 0; chunk < 4; ++chunk) {
#pragma unroll
        for (int it = 0; it < 4; ++it) {
            int i   = it * 256 + tid;
            int row = i >> 3;
            int kq  = (i & 7) * 4;
            int c0  = nc_map(kq / 2);
            int c1  = nc_map(kq / 2 + 1);
            uint32_t h0, l0, h1, l1;
            split_pack(ra[it].x, ra[it].y, h0, l0);
            split_pack(ra[it].z, ra[it].w, h1, l1);
            AsHi[row][c0] = h0; AsLo[row][c0] = l0;
            AsHi[row][c1] = h1; AsLo[row][c1] = l1;
            split_pack(rbv[it].x, rbv[it].y, h0, l0);
            split_pack(rbv[it].z, rbv[it].w, h1, l1);
            BsHi[row][c0] = h0; BsLo[row][c0] = l0;
            BsHi[row][c1] = h1; BsLo[row][c1] = l1;
        }
        __syncthreads();

        if (chunk < 3) {
            const int ks = (chunk + 1) * 32;
#pragma unroll
            for (int it = 0; it < 4; ++it) {
                int i   = it * 256 + tid;
                int row = i >> 3;
                int kq  = (i & 7) * 4;
                int gr  = rb + row;
                ra[it] = make_float4(0.f, 0.f, 0.f, 0.f);
                if (gr < NN) ra[it] = *(const float4*)&feats[(size_t)gr * CIN + ks + kq];
            }
#pragma unroll
            for (int it = 0; it < 4; ++it) {
                int i   = it * 256 + tid;
                int col = i >> 3;
                int kq  = (i & 7) * 4;
                int gc  = cb + col;
                const float* wp = (gc < CTOT) ? &fcw[(size_t)gc * CIN]
                                              : &resw[(size_t)(gc - CTOT) * CIN];
                rbv[it] = *(const float4*)&wp[ks + kq];
            }
        }

#pragma unroll
        for (int k2b = 0; k2b < 16; k2b += 8) {
            const int kc = k2b + 2 * qcol;       // interleaved pair column
            uint32_t aH[2][4], aL[2][4];
#pragma unroll
            for (int mt = 0; mt < 2; ++mt) {
                int rw = wm * 32 + mt * 16 + qrow;
                uint2 vh0 = *(const uint2*)&AsHi[rw][kc];
                uint2 vh1 = *(const uint2*)&AsHi[rw + 8][kc];
                uint2 vl0 = *(const uint2*)&AsLo[rw][kc];
                uint2 vl1 = *(const uint2*)&AsLo[rw + 8][kc];
                aH[mt][0] = vh0.x; aH[mt][2] = vh0.y;
                aH[mt][1] = vh1.x; aH[mt][3] = vh1.y;
                aL[mt][0] = vl0.x; aL[mt][2] = vl0.y;
                aL[mt][1] = vl1.x; aL[mt][3] = vl1.y;
            }
#pragma unroll
            for (int nt = 0; nt < 8; ++nt) {
                int cl = wn * 64 + nt * 8 + qrow;
                uint2 bh = *(const uint2*)&BsHi[cl][kc];
                uint2 bl = *(const uint2*)&BsLo[cl][kc];
#pragma unroll
                for (int mt = 0; mt < 2; ++mt) {
                    mma_bf16(c[mt][nt], aH[mt], bh.x, bh.y);
                    mma_bf16(c[mt][nt], aH[mt], bl.x, bl.y);
                    mma_bf16(c[mt][nt], aL[mt], bh.x, bh.y);
                }
            }
        }
        __syncthreads();
    }

    // epilogue: h -> fp16, res -> fp32
#pragma unroll
    for (int mt = 0; mt < 2; ++mt) {
        int r = rb + wm * 32 + mt * 16 + qrow;
#pragma unroll
        for (int nt = 0; nt < 8; ++nt) {
            int cg = cb + wn * 64 + nt * 8 + qcol * 2;
            if (cg < CTOT) {
                if (r < NN)
                    *(__half2*)&g_h[(size_t)r * CTOT + cg] =
                        __floats2half2_rn(c[mt][nt][0], c[mt][nt][1]);
                if (r + 8 < NN)
                    *(__half2*)&g_h[(size_t)(r + 8) * CTOT + cg] =
                        __floats2half2_rn(c[mt][nt][2], c[mt][nt][3]);
            } else {
                int cc = cg - CTOT;
                if (r < NN)
                    *(float2*)&g_res[(size_t)r * CTOT + cc] =
                        make_float2(c[mt][nt][0], c[mt][nt][1]);
                if (r + 8 < NN)
                    *(float2*)&g_res[(size_t)(r + 8) * CTOT + cc] =
                        make_float2(c[mt][nt][2], c[mt][nt][3]);
            }
        }
    }

    // fused el/er: warp tile = exactly one head (64 cols)
    if (cb < CTOT) {
        const int head = (cb >> 6) + wn;
#pragma unroll
        for (int mt = 0; mt < 2; ++mt) {
            float pl0 = 0.f, pr0 = 0.f, pl8 = 0.f, pr8 = 0.f;
#pragma unroll
            for (int nt = 0; nt < 8; ++nt) {
                int cg = cb + wn * 64 + nt * 8 + qcol * 2;
                float a0 = al[cg], a1 = al[cg + 1];
                float r0 = ar[cg], r1 = ar[cg + 1];
                pl0 += c[mt][nt][0] * a0 + c[mt][nt][1] * a1;
                pr0 += c[mt][nt][0] * r0 + c[mt][nt][1] * r1;
                pl8 += c[mt][nt][2] * a0 + c[mt][nt][3] * a1;
                pr8 += c[mt][nt][2] * r0 + c[mt][nt][3] * r1;
            }
#pragma unroll
            for (int o = 1; o <= 2; o <<= 1) {
                pl0 += __shfl_xor_sync(0xffffffffu, pl0, o);
                pr0 += __shfl_xor_sync(0xffffffffu, pr0, o);
                pl8 += __shfl_xor_sync(0xffffffffu, pl8, o);
                pr8 += __shfl_xor_sync(0xffffffffu, pr8, o);
            }
            if (qcol == 0) {
                int r = rb + wm * 32 + mt * 16 + qrow;
                if (r < NN)     { g_el[r * NH + head] = pl0; g_er[r * NH + head] = pr0; }
                if (r + 8 < NN) { g_el[(r + 8) * NH + head] = pl8; g_er[(r + 8) * NH + head] = pr8; }
            }
        }
    }
}

// dst histogram (int4-vectorized)
__global__ void hist_kernel(const int* __restrict__ dst) {
    int i = blockIdx.x * blockDim.x + threadIdx.x;
    int i4 = i * 4;
    if (i4 + 3 < NE) {
        int4 d = *(const int4*)&dst[i4];
        atomicAdd(&g_cnt[d.x], 1);
        atomicAdd(&g_cnt[d.y], 1);
        atomicAdd(&g_cnt[d.z], 1);
        atomicAdd(&g_cnt[d.w], 1);
    } else {
        for (int j = i4; j < NE; ++j) atomicAdd(&g_cnt[dst[j]], 1);
    }
}

// 3-kernel exclusive scan of g_cnt -> g_off (+ g_cur copy)
__global__ void scan1_kernel() {
    __shared__ int sd[1024];
    int t = threadIdx.x;
    int gid = blockIdx.x * 1024 + t;
    int v = (gid < NN) ? g_cnt[gid] : 0;
    sd[t] = v; __syncthreads();
    for (int o = 1; o < 1024; o <<= 1) {
        int x = (t >= o) ? sd[t - o] : 0;
        __syncthreads();
        sd[t] += x;
        __syncthreads();
    }
    if (gid < NN) g_off[gid] = sd[t] - v;
    if (t == 1023) g_bsum[blockIdx.x] = sd[1023];
}
__global__ void scan2_kernel() {
    __shared__ int sd[128];
    int t = threadIdx.x;
    int v = (t < SCAN_B) ? g_bsum[t] : 0;
    sd[t] = v; __syncthreads();
    for (int o = 1; o < 128; o <<= 1) {
        int x = (t >= o) ? sd[t - o] : 0;
        __syncthreads();
        sd[t] += x;
        __syncthreads();
    }
    if (t < SCAN_B) g_bsum[t] = sd[t] - v;
}
__global__ void scan3_kernel() {
    int gid = blockIdx.x * 1024 + threadIdx.x;
    if (gid < NN) {
        int o = g_off[gid] + g_bsum[blockIdx.x];
        g_off[gid] = o;
        g_cur[gid] = o;
    }
    if (gid == 0) g_off[NN] = NE;
}

// edge pass: ex = exp(lrelu(el+er)) -> fp16, counting-sort by dst.
__global__ void scatter_kernel(const int* __restrict__ src,
                               const int* __restrict__ dst) {
    int i = blockIdx.x * blockDim.x + threadIdx.x;
    if (i >= NE) return;
    int s = src[i], d = dst[i];
    float4 a = *(const float4*)&g_el[s * NH];
    float4 b = *(const float4*)&g_er[d * NH];
    float t;
    t = a.x + b.x; t = t > 0.f ? t : NEG_SLOPE * t; __half e0 = __float2half(__expf(t));
    t = a.y + b.y; t = t > 0.f ? t : NEG_SLOPE * t; __half e1 = __float2half(__expf(t));
    t = a.z + b.z; t = t > 0.f ? t : NEG_SLOPE * t; __half e2 = __float2half(__expf(t));
    t = a.w + b.w; t = t > 0.f ? t : NEG_SLOPE * t; __half e3 = __float2half(__expf(t));
    int p = atomicAdd(&g_cur[d], 1);
    __half2 p01 = __halves2half2(e0, e1);
    __half2 p23 = __halves2half2(e2, e3);
    g_ssrc[p] = s;
    g_sexh[p] = make_uint2(*(uint32_t*)&p01, *(uint32_t*)&p23);
}

// aggregation + in-register denom + residual + bias + ELU + mean + BN partials.
// One warp/node; thread: 2 heads x 4 d-elems; edge loop unrolled x2.
__global__ __launch_bounds__(256) void agg_kernel(const float* __restrict__ bias,
                                                  float* __restrict__ out) {
    __shared__ float sSum[DD], sSS[DD];
    if (threadIdx.x < DD) { sSum[threadIdx.x] = 0.f; sSS[threadIdx.x] = 0.f; }
    __syncthreads();

    int node = blockIdx.x * 8 + (threadIdx.x >> 5);   // NN % 8 == 0: all valid
    int lane = threadIdx.x & 31;
    int grp = lane >> 4;
    int idx = lane & 15;
    int offA = grp * 64 + idx * 4;
    int offB = (grp + 2) * 64 + idx * 4;
    int beg = g_off[node], end = g_off[node + 1];

    float4 accA = make_float4(0.f, 0.f, 0.f, 0.f);
    float4 accB = make_float4(0.f, 0.f, 0.f, 0.f);
    float sA = 0.f, sB = 0.f;

    int e = beg;
#pragma unroll 1
    for (; e + 1 < end; e += 2) {
        int s0 = g_ssrc[e], s1 = g_ssrc[e + 1];
        uint2 w0 = g_sexh[e], w1 = g_sexh[e + 1];
        const __half* hp0 = &g_h[(size_t)s0 * CTOT];
        const __half* hp1 = &g_h[(size_t)s1 * CTOT];
        uint2 ra0 = *(const uint2*)&hp0[offA];
        uint2 rb0 = *(const uint2*)&hp0[offB];
        uint2 ra1 = *(const uint2*)&hp1[offA];
        uint2 rb1 = *(const uint2*)&hp1[offB];
        float wA0 = grp ? __high2float(*(__half2*)&w0.x) : __low2float(*(__half2*)&w0.x);
        float wB0 = grp ? __high2float(*(__half2*)&w0.y) : __low2float(*(__half2*)&w0.y);
        float wA1 = grp ? __high2float(*(__half2*)&w1.x) : __low2float(*(__half2*)&w1.x);
        float wB1 = grp ? __high2float(*(__half2*)&w1.y) : __low2float(*(__half2*)&w1.y);
        sA += wA0 + wA1; sB += wB0 + wB1;
        float2 t0, t1;
        t0 = __half22float2(*(__half2*)&ra0.x); accA.x += wA0 * t0.x; accA.y += wA0 * t0.y;
        t1 = __half22float2(*(__half2*)&ra0.y); accA.z += wA0 * t1.x; accA.w += wA0 * t1.y;
        t0 = __half22float2(*(__half2*)&rb0.x); accB.x += wB0 * t0.x; accB.y += wB0 * t0.y;
        t1 = __half22float2(*(__half2*)&rb0.y); accB.z += wB0 * t1.x; accB.w += wB0 * t1.y;
        t0 = __half22float2(*(__half2*)&ra1.x); accA.x += wA1 * t0.x; accA.y += wA1 * t0.y;
        t1 = __half22float2(*(__half2*)&ra1.y); accA.z += wA1 * t1.x; accA.w += wA1 * t1.y;
        t0 = __half22float2(*(__half2*)&rb1.x); accB.x += wB1 * t0.x; accB.y += wB1 * t0.y;
        t1 = __half22float2(*(__half2*)&rb1.y); accB.z += wB1 * t1.x; accB.w += wB1 * t1.y;
    }
    if (e < end) {
        int s0 = g_ssrc[e];
        uint2 w0 = g_sexh[e];
        const __half* hp0 = &g_h[(size_t)s0 * CTOT];
        uint2 ra0 = *(const uint2*)&hp0[offA];
        uint2 rb0 = *(const uint2*)&hp0[offB];
        float wA0 = grp ? __high2float(*(__half2*)&w0.x) : __low2float(*(__half2*)&w0.x);
        float wB0 = grp ? __high2float(*(__half2*)&w0.y) : __low2float(*(__half2*)&w0.y);
        sA += wA0; sB += wB0;
        float2 t0, t1;
        t0 = __half22float2(*(__half2*)&ra0.x); accA.x += wA0 * t0.x; accA.y += wA0 * t0.y;
        t1 = __half22float2(*(__half2*)&ra0.y); accA.z += wA0 * t1.x; accA.w += wA0 * t1.y;
        t0 = __half22float2(*(__half2*)&rb0.x); accB.x += wB0 * t0.x; accB.y += wB0 * t0.y;
        t1 = __half22float2(*(__half2*)&rb0.y); accB.z += wB0 * t1.x; accB.w += wB0 * t1.y;
    }

    float invA = (sA > 0.f) ? 1.f / sA : 0.f;
    float invB = (sB > 0.f) ? 1.f / sB : 0.f;
    const float* rp = &g_res[(size_t)node * CTOT];
    float4 rA = *(const float4*)&rp[offA];
    float4 rB = *(const float4*)&rp[offB];
    float4 bA = *(const float4*)&bias[offA];
    float4 bB = *(const float4*)&bias[offB];
    float4 tot;
    tot.x = elu1(accA.x * invA + rA.x + bA.x) + elu1(accB.x * invB + rB.x + bB.x);
    tot.y = elu1(accA.y * invA + rA.y + bA.y) + elu1(accB.y * invB + rB.y + bB.y);
    tot.z = elu1(accA.z * invA + rA.z + bA.z) + elu1(accB.z * invB + rB.z + bB.z);
    tot.w = elu1(accA.w * invA + rA.w + bA.w) + elu1(accB.w * invB + rB.w + bB.w);
    tot.x += __shfl_xor_sync(0xffffffffu, tot.x, 16);
    tot.y += __shfl_xor_sync(0xffffffffu, tot.y, 16);
    tot.z += __shfl_xor_sync(0xffffffffu, tot.z, 16);
    tot.w += __shfl_xor_sync(0xffffffffu, tot.w, 16);
    if (grp == 0) {
        float4 o = make_float4(tot.x * 0.25f, tot.y * 0.25f,
                               tot.z * 0.25f, tot.w * 0.25f);
        *(float4*)&out[(size_t)node * DD + idx * 4] = o;
        int d0 = idx * 4;
        atomicAdd(&sSum[d0 + 0], o.x); atomicAdd(&sSS[d0 + 0], o.x * o.x);
        atomicAdd(&sSum[d0 + 1], o.y); atomicAdd(&sSS[d0 + 1], o.y * o.y);
        atomicAdd(&sSum[d0 + 2], o.z); atomicAdd(&sSS[d0 + 2], o.z * o.z);
        atomicAdd(&sSum[d0 + 3], o.w); atomicAdd(&sSS[d0 + 3], o.w * o.w);
    }
    __syncthreads();
    if (threadIdx.x < DD) {
        atomicAdd(&g_bnsum[threadIdx.x], sSum[threadIdx.x]);
        atomicAdd(&g_bnss[threadIdx.x],  sSS[threadIdx.x]);
    }
}

__global__ void bnapply_kernel(float* __restrict__ out,
                               const float* __restrict__ gamma,
                               const float* __restrict__ beta) {
    int gid = blockIdx.x * blockDim.x + threadIdx.x;
    if (gid >= NN * DD) return;
    int d = gid & 63;
    const float invn = 1.f / (float)NN;
    float mu  = g_bnsum[d] * invn;
    float var = g_bnss[d] * invn - mu * mu;
    out[gid] = (out[gid] - mu) * rsqrtf(var + BN_EPS) * gamma[d] + beta[d];
}

// ---------------- launch ----------------
extern "C" void kernel_launch(void* const* d_in, const int* in_sizes, int n_in,
                              void* d_out, int out_size) {
    const float* feats = (const float*)d_in[0];
    const int*   src   = (const int*)d_in[1];
    const int*   dst   = (const int*)d_in[2];
    const float* fcw   = (const float*)d_in[3];
    const float* al    = (const float*)d_in[4];
    const float* ar    = (const float*)d_in[5];
    const float* resw  = (const float*)d_in[6];
    const float* bias  = (const float*)d_in[7];
    const float* gamma = (const float*)d_in[8];
    const float* beta  = (const float*)d_in[9];
    float* out = (float*)d_out;

    zero_kernel<<<(NN + 255) / 256, 256>>>();
    gemm_bf16_kernel<<<dim3(4, (NN + 127) / 128), 256>>>(feats, fcw, resw, al, ar);
    hist_kernel<<<(NE / 4 + 255) / 256, 256>>>(dst);
    scan1_kernel<<<SCAN_B, 1024>>>();
    scan2_kernel<<<1, 128>>>();
    scan3_kernel<<<SCAN_B, 1024>>>();
    scatter_kernel<<<(NE + 255) / 256, 256>>>(src, dst);
    agg_kernel<<<NN / 8, 256>>>(bias, out);
    bnapply_kernel<<<(NN * DD + 255) / 256, 256>>>(out, gamma, beta);
}

// round 13
// speedup vs baseline: 1.0905x; 1.0380x over previous
#include <cuda_runtime.h>
#include <cuda_fp16.h>
#include <cuda_bf16.h>
#include <cstdint>

// ---------------- problem constants ----------------
namespace {
constexpr int NN   = 100000;
constexpr int NE   = 1600000;
constexpr int NH   = 4;
constexpr int DD   = 64;
constexpr int CIN  = 128;
constexpr int CTOT = 256;
constexpr float NEG_SLOPE = 0.2f;
constexpr float BN_EPS    = 1e-5f;
constexpr int SCAN_B = (NN + 1023) / 1024;
}

// ---------------- scratch ----------------
__device__ __align__(16) __half g_h   [(size_t)NN * CTOT];  // projected feats (fp16)
__device__ __align__(16) __half g_resh[(size_t)NN * CTOT];  // residual proj (fp16)
__device__ __align__(16) float  g_el [NN * NH];
__device__ __align__(16) float  g_er [NN * NH];
__device__ int                  g_cnt[NN];
__device__ int                  g_off[NN + 1];
__device__ int                  g_cur[NN];
__device__ int                  g_ssrc[NE];                 // src sorted by dst
__device__ uint2                g_sexh[NE];                 // ex (4 x fp16) sorted by dst
__device__ float                g_bnsum[DD];
__device__ float                g_bnss [DD];
__device__ int                  g_bsum[128];

// ---------------- helpers ----------------
__device__ __forceinline__ void mma_bf16(float* c, const uint32_t* a,
                                         uint32_t b0, uint32_t b1) {
    asm volatile(
        "mma.sync.aligned.m16n8k16.row.col.f32.bf16.bf16.f32 "
        "{%0,%1,%2,%3},{%4,%5,%6,%7},{%8,%9},{%0,%1,%2,%3};"
        : "+f"(c[0]), "+f"(c[1]), "+f"(c[2]), "+f"(c[3])
        : "r"(a[0]), "r"(a[1]), "r"(a[2]), "r"(a[3]), "r"(b0), "r"(b1));
}
__device__ __forceinline__ void split_pack(float x, float y,
                                           uint32_t& hi, uint32_t& lo) {
    __nv_bfloat16 hx = __float2bfloat16(x);
    __nv_bfloat16 hy = __float2bfloat16(y);
    __nv_bfloat16 lx = __float2bfloat16(x - __bfloat162float(hx));
    __nv_bfloat16 ly = __float2bfloat16(y - __bfloat162float(hy));
    __nv_bfloat162 h2 = __nv_bfloat162(hx, hy);
    __nv_bfloat162 l2 = __nv_bfloat162(lx, ly);
    hi = *(uint32_t*)&h2;
    lo = *(uint32_t*)&l2;
}
__device__ __forceinline__ float elu1(float v) {
    return v > 0.f ? v : (__expf(v) - 1.f);
}
// k2-column interleave: within each 8-block, (q, q+4) -> (2q, 2q+1)
// so fragment pairs ([k],[k+4]) are adjacent -> LDS.64 loads.
__device__ __forceinline__ int nc_map(int k2) {
    return (k2 & 8) | (((k2 & 3) << 1) | ((k2 >> 2) & 1));
}

// ---------------- kernels ----------------

__global__ void zero_kernel() {
    int i = blockIdx.x * blockDim.x + threadIdx.x;
    if (i < NN) g_cnt[i] = 0;
    if (i < DD) { g_bnsum[i] = 0.f; g_bnss[i] = 0.f; }
}

// bf16x3 split tensor-core GEMM + fused el/er epilogue.
// Block 128x128, BK=32, 8 warps (4m x 2n), warp tile 32x64 (= one head wide).
__global__ __launch_bounds__(256) void gemm_bf16_kernel(
        const float* __restrict__ feats,
        const float* __restrict__ fcw,
        const float* __restrict__ resw,
        const float* __restrict__ al,
        const float* __restrict__ ar) {
    __shared__ __align__(16) uint32_t AsHi[128][20], AsLo[128][20];
    __shared__ __align__(16) uint32_t BsHi[128][20], BsLo[128][20];

    const int tid  = threadIdx.x;
    const int lane = tid & 31;
    const int w    = tid >> 5;
    const int wm   = w & 3;
    const int wn   = w >> 2;
    const int rb   = blockIdx.y * 128;
    const int cb   = blockIdx.x * 128;

    float c[2][8][4];
#pragma unroll
    for (int mt = 0; mt < 2; ++mt)
#pragma unroll
        for (int nt = 0; nt < 8; ++nt)
#pragma unroll
            for (int q = 0; q < 4; ++q) c[mt][nt][q] = 0.f;

    const int qrow = lane >> 2;
    const int qcol = lane & 3;

    float4 ra[4], rbv[4];
    {
#pragma unroll
        for (int it = 0; it < 4; ++it) {
            int i   = it * 256 + tid;
            int row = i >> 3;
            int kq  = (i & 7) * 4;
            int gr  = rb + row;
            ra[it] = make_float4(0.f, 0.f, 0.f, 0.f);
            if (gr < NN) ra[it] = *(const float4*)&feats[(size_t)gr * CIN + kq];
        }
#pragma unroll
        for (int it = 0; it < 4; ++it) {
            int i   = it * 256 + tid;
            int col = i >> 3;
            int kq  = (i & 7) * 4;
            int gc  = cb + col;
            const float* wp = (gc < CTOT) ? &fcw[(size_t)gc * CIN]
                                          : &resw[(size_t)(gc - CTOT) * CIN];
            rbv[it] = *(const float4*)&wp[kq];
        }
    }

#pragma unroll
    for (int chunk = 0; chunk < 4; ++chunk) {
#pragma unroll
        for (int it = 0; it < 4; ++it) {
            int i   = it * 256 + tid;
            int row = i >> 3;
            int kq  = (i & 7) * 4;
            int c0  = nc_map(kq / 2);
            int c1  = nc_map(kq / 2 + 1);
            uint32_t h0, l0, h1, l1;
            split_pack(ra[it].x, ra[it].y, h0, l0);
            split_pack(ra[it].z, ra[it].w, h1, l1);
            AsHi[row][c0] = h0; AsLo[row][c0] = l0;
            AsHi[row][c1] = h1; AsLo[row][c1] = l1;
            split_pack(rbv[it].x, rbv[it].y, h0, l0);
            split_pack(rbv[it].z, rbv[it].w, h1, l1);
            BsHi[row][c0] = h0; BsLo[row][c0] = l0;
            BsHi[row][c1] = h1; BsLo[row][c1] = l1;
        }
        __syncthreads();

        if (chunk < 3) {
            const int ks = (chunk + 1) * 32;
#pragma unroll
            for (int it = 0; it < 4; ++it) {
                int i   = it * 256 + tid;
                int row = i >> 3;
                int kq  = (i & 7) * 4;
                int gr  = rb + row;
                ra[it] = make_float4(0.f, 0.f, 0.f, 0.f);
                if (gr < NN) ra[it] = *(const float4*)&feats[(size_t)gr * CIN + ks + kq];
            }
#pragma unroll
            for (int it = 0; it < 4; ++it) {
                int i   = it * 256 + tid;
                int col = i >> 3;
                int kq  = (i & 7) * 4;
                int gc  = cb + col;
                const float* wp = (gc < CTOT) ? &fcw[(size_t)gc * CIN]
                                              : &resw[(size_t)(gc - CTOT) * CIN];
                rbv[it] = *(const float4*)&wp[ks + kq];
            }
        }

#pragma unroll
        for (int k2b = 0; k2b < 16; k2b += 8) {
            const int kc = k2b + 2 * qcol;       // interleaved pair column
            uint32_t aH[2][4], aL[2][4];
#pragma unroll
            for (int mt = 0; mt < 2; ++mt) {
                int rw = wm * 32 + mt * 16 + qrow;
                uint2 vh0 = *(const uint2*)&AsHi[rw][kc];
                uint2 vh1 = *(const uint2*)&AsHi[rw + 8][kc];
                uint2 vl0 = *(const uint2*)&AsLo[rw][kc];
                uint2 vl1 = *(const uint2*)&AsLo[rw + 8][kc];
                aH[mt][0] = vh0.x; aH[mt][2] = vh0.y;
                aH[mt][1] = vh1.x; aH[mt][3] = vh1.y;
                aL[mt][0] = vl0.x; aL[mt][2] = vl0.y;
                aL[mt][1] = vl1.x; aL[mt][3] = vl1.y;
            }
#pragma unroll
            for (int nt = 0; nt < 8; ++nt) {
                int cl = wn * 64 + nt * 8 + qrow;
                uint2 bh = *(const uint2*)&BsHi[cl][kc];
                uint2 bl = *(const uint2*)&BsLo[cl][kc];
#pragma unroll
                for (int mt = 0; mt < 2; ++mt) {
                    mma_bf16(c[mt][nt], aH[mt], bh.x, bh.y);
                    mma_bf16(c[mt][nt], aH[mt], bl.x, bl.y);
                    mma_bf16(c[mt][nt], aL[mt], bh.x, bh.y);
                }
            }
        }
        __syncthreads();
    }

    // epilogue: h -> fp16, res -> fp16
#pragma unroll
    for (int mt = 0; mt < 2; ++mt) {
        int r = rb + wm * 32 + mt * 16 + qrow;
#pragma unroll
        for (int nt = 0; nt < 8; ++nt) {
            int cg = cb + wn * 64 + nt * 8 + qcol * 2;
            __half* base = (cg < CTOT) ? g_h : g_resh;
            int cc = (cg < CTOT) ? cg : cg - CTOT;
            if (r < NN)
                *(__half2*)&base[(size_t)r * CTOT + cc] =
                    __floats2half2_rn(c[mt][nt][0], c[mt][nt][1]);
            if (r + 8 < NN)
                *(__half2*)&base[(size_t)(r + 8) * CTOT + cc] =
                    __floats2half2_rn(c[mt][nt][2], c[mt][nt][3]);
        }
    }

    // fused el/er: warp tile = exactly one head (64 cols)
    if (cb < CTOT) {
        const int head = (cb >> 6) + wn;
#pragma unroll
        for (int mt = 0; mt < 2; ++mt) {
            float pl0 = 0.f, pr0 = 0.f, pl8 = 0.f, pr8 = 0.f;
#pragma unroll
            for (int nt = 0; nt < 8; ++nt) {
                int cg = cb + wn * 64 + nt * 8 + qcol * 2;
                float a0 = al[cg], a1 = al[cg + 1];
                float r0 = ar[cg], r1 = ar[cg + 1];
                pl0 += c[mt][nt][0] * a0 + c[mt][nt][1] * a1;
                pr0 += c[mt][nt][0] * r0 + c[mt][nt][1] * r1;
                pl8 += c[mt][nt][2] * a0 + c[mt][nt][3] * a1;
                pr8 += c[mt][nt][2] * r0 + c[mt][nt][3] * r1;
            }
#pragma unroll
            for (int o = 1; o <= 2; o <<= 1) {
                pl0 += __shfl_xor_sync(0xffffffffu, pl0, o);
                pr0 += __shfl_xor_sync(0xffffffffu, pr0, o);
                pl8 += __shfl_xor_sync(0xffffffffu, pl8, o);
                pr8 += __shfl_xor_sync(0xffffffffu, pr8, o);
            }
            if (qcol == 0) {
                int r = rb + wm * 32 + mt * 16 + qrow;
                if (r < NN)     { g_el[r * NH + head] = pl0; g_er[r * NH + head] = pr0; }
                if (r + 8 < NN) { g_el[(r + 8) * NH + head] = pl8; g_er[(r + 8) * NH + head] = pr8; }
            }
        }
    }
}

// dst histogram (int4-vectorized)
__global__ void hist_kernel(const int* __restrict__ dst) {
    int i = blockIdx.x * blockDim.x + threadIdx.x;
    int i4 = i * 4;
    if (i4 + 3 < NE) {
        int4 d = *(const int4*)&dst[i4];
        atomicAdd(&g_cnt[d.x], 1);
        atomicAdd(&g_cnt[d.y], 1);
        atomicAdd(&g_cnt[d.z], 1);
        atomicAdd(&g_cnt[d.w], 1);
    } else {
        for (int j = i4; j < NE; ++j) atomicAdd(&g_cnt[dst[j]], 1);
    }
}

// 3-kernel exclusive scan of g_cnt -> g_off (+ g_cur copy)
__global__ void scan1_kernel() {
    __shared__ int sd[1024];
    int t = threadIdx.x;
    int gid = blockIdx.x * 1024 + t;
    int v = (gid < NN) ? g_cnt[gid] : 0;
    sd[t] = v; __syncthreads();
    for (int o = 1; o < 1024; o <<= 1) {
        int x = (t >= o) ? sd[t - o] : 0;
        __syncthreads();
        sd[t] += x;
        __syncthreads();
    }
    if (gid < NN) g_off[gid] = sd[t] - v;
    if (t == 1023) g_bsum[blockIdx.x] = sd[1023];
}
__global__ void scan2_kernel() {
    __shared__ int sd[128];
    int t = threadIdx.x;
    int v = (t < SCAN_B) ? g_bsum[t] : 0;
    sd[t] = v; __syncthreads();
    for (int o = 1; o < 128; o <<= 1) {
        int x = (t >= o) ? sd[t - o] : 0;
        __syncthreads();
        sd[t] += x;
        __syncthreads();
    }
    if (t < SCAN_B) g_bsum[t] = sd[t] - v;
}
__global__ void scan3_kernel() {
    int gid = blockIdx.x * 1024 + threadIdx.x;
    if (gid < NN) {
        int o = g_off[gid] + g_bsum[blockIdx.x];
        g_off[gid] = o;
        g_cur[gid] = o;
    }
    if (gid == 0) g_off[NN] = NE;
}

// edge pass: ex = exp(lrelu(el+er)) -> fp16, counting-sort by dst.
__global__ void scatter_kernel(const int* __restrict__ src,
                               const int* __restrict__ dst) {
    int i = blockIdx.x * blockDim.x + threadIdx.x;
    if (i >= NE) return;
    int s = src[i], d = dst[i];
    float4 a = *(const float4*)&g_el[s * NH];
    float4 b = *(const float4*)&g_er[d * NH];
    float t;
    t = a.x + b.x; t = t > 0.f ? t : NEG_SLOPE * t; __half e0 = __float2half(__expf(t));
    t = a.y + b.y; t = t > 0.f ? t : NEG_SLOPE * t; __half e1 = __float2half(__expf(t));
    t = a.z + b.z; t = t > 0.f ? t : NEG_SLOPE * t; __half e2 = __float2half(__expf(t));
    t = a.w + b.w; t = t > 0.f ? t : NEG_SLOPE * t; __half e3 = __float2half(__expf(t));
    int p = atomicAdd(&g_cur[d], 1);
    __half2 p01 = __halves2half2(e0, e1);
    __half2 p23 = __halves2half2(e2, e3);
    g_ssrc[p] = s;
    g_sexh[p] = make_uint2(*(uint32_t*)&p01, *(uint32_t*)&p23);
}

// aggregation + in-register denom + residual + bias + ELU + mean + BN partials.
// One warp/node; thread: 2 heads x 4 d-elems; edge loop unrolled x2.
__global__ __launch_bounds__(256) void agg_kernel(const float* __restrict__ bias,
                                                  float* __restrict__ out) {
    __shared__ float sSum[DD], sSS[DD];
    if (threadIdx.x < DD) { sSum[threadIdx.x] = 0.f; sSS[threadIdx.x] = 0.f; }
    __syncthreads();

    int node = blockIdx.x * 8 + (threadIdx.x >> 5);   // NN % 8 == 0
    int lane = threadIdx.x & 31;
    int grp = lane >> 4;
    int idx = lane & 15;
    int offA = grp * 64 + idx * 4;
    int offB = (grp + 2) * 64 + idx * 4;
    int beg = g_off[node], end = g_off[node + 1];

    float4 accA = make_float4(0.f, 0.f, 0.f, 0.f);
    float4 accB = make_float4(0.f, 0.f, 0.f, 0.f);
    float sA = 0.f, sB = 0.f;

    int e = beg;
#pragma unroll 1
    for (; e + 1 < end; e += 2) {
        int s0 = g_ssrc[e], s1 = g_ssrc[e + 1];
        uint2 w0 = g_sexh[e], w1 = g_sexh[e + 1];
        const __half* hp0 = &g_h[(size_t)s0 * CTOT];
        const __half* hp1 = &g_h[(size_t)s1 * CTOT];
        uint2 ra0 = *(const uint2*)&hp0[offA];
        uint2 rb0 = *(const uint2*)&hp0[offB];
        uint2 ra1 = *(const uint2*)&hp1[offA];
        uint2 rb1 = *(const uint2*)&hp1[offB];
        float wA0 = grp ? __high2float(*(__half2*)&w0.x) : __low2float(*(__half2*)&w0.x);
        float wB0 = grp ? __high2float(*(__half2*)&w0.y) : __low2float(*(__half2*)&w0.y);
        float wA1 = grp ? __high2float(*(__half2*)&w1.x) : __low2float(*(__half2*)&w1.x);
        float wB1 = grp ? __high2float(*(__half2*)&w1.y) : __low2float(*(__half2*)&w1.y);
        sA += wA0 + wA1; sB += wB0 + wB1;
        float2 t0, t1;
        t0 = __half22float2(*(__half2*)&ra0.x); accA.x += wA0 * t0.x; accA.y += wA0 * t0.y;
        t1 = __half22float2(*(__half2*)&ra0.y); accA.z += wA0 * t1.x; accA.w += wA0 * t1.y;
        t0 = __half22float2(*(__half2*)&rb0.x); accB.x += wB0 * t0.x; accB.y += wB0 * t0.y;
        t1 = __half22float2(*(__half2*)&rb0.y); accB.z += wB0 * t1.x; accB.w += wB0 * t1.y;
        t0 = __half22float2(*(__half2*)&ra1.x); accA.x += wA1 * t0.x; accA.y += wA1 * t0.y;
        t1 = __half22float2(*(__half2*)&ra1.y); accA.z += wA1 * t1.x; accA.w += wA1 * t1.y;
        t0 = __half22float2(*(__half2*)&rb1.x); accB.x += wB1 * t0.x; accB.y += wB1 * t0.y;
        t1 = __half22float2(*(__half2*)&rb1.y); accB.z += wB1 * t1.x; accB.w += wB1 * t1.y;
    }
    if (e < end) {
        int s0 = g_ssrc[e];
        uint2 w0 = g_sexh[e];
        const __half* hp0 = &g_h[(size_t)s0 * CTOT];
        uint2 ra0 = *(const uint2*)&hp0[offA];
        uint2 rb0 = *(const uint2*)&hp0[offB];
        float wA0 = grp ? __high2float(*(__half2*)&w0.x) : __low2float(*(__half2*)&w0.x);
        float wB0 = grp ? __high2float(*(__half2*)&w0.y) : __low2float(*(__half2*)&w0.y);
        sA += wA0; sB += wB0;
        float2 t0, t1;
        t0 = __half22float2(*(__half2*)&ra0.x); accA.x += wA0 * t0.x; accA.y += wA0 * t0.y;
        t1 = __half22float2(*(__half2*)&ra0.y); accA.z += wA0 * t1.x; accA.w += wA0 * t1.y;
        t0 = __half22float2(*(__half2*)&rb0.x); accB.x += wB0 * t0.x; accB.y += wB0 * t0.y;
        t1 = __half22float2(*(__half2*)&rb0.y); accB.z += wB0 * t1.x; accB.w += wB0 * t1.y;
    }

    float invA = (sA > 0.f) ? 1.f / sA : 0.f;
    float invB = (sB > 0.f) ? 1.f / sB : 0.f;
    const __half* rp = &g_resh[(size_t)node * CTOT];
    uint2 rAu = *(const uint2*)&rp[offA];
    uint2 rBu = *(const uint2*)&rp[offB];
    float2 rA0 = __half22float2(*(__half2*)&rAu.x);
    float2 rA1 = __half22float2(*(__half2*)&rAu.y);
    float2 rB0 = __half22float2(*(__half2*)&rBu.x);
    float2 rB1 = __half22float2(*(__half2*)&rBu.y);
    float4 bA = *(const float4*)&bias[offA];
    float4 bB = *(const float4*)&bias[offB];
    float4 tot;
    tot.x = elu1(accA.x * invA + rA0.x + bA.x) + elu1(accB.x * invB + rB0.x + bB.x);
    tot.y = elu1(accA.y * invA + rA0.y + bA.y) + elu1(accB.y * invB + rB0.y + bB.y);
    tot.z = elu1(accA.z * invA + rA1.x + bA.z) + elu1(accB.z * invB + rB1.x + bB.z);
    tot.w = elu1(accA.w * invA + rA1.y + bA.w) + elu1(accB.w * invB + rB1.y + bB.w);
    tot.x += __shfl_xor_sync(0xffffffffu, tot.x, 16);
    tot.y += __shfl_xor_sync(0xffffffffu, tot.y, 16);
    tot.z += __shfl_xor_sync(0xffffffffu, tot.z, 16);
    tot.w += __shfl_xor_sync(0xffffffffu, tot.w, 16);
    if (grp == 0) {
        float4 o = make_float4(tot.x * 0.25f, tot.y * 0.25f,
                               tot.z * 0.25f, tot.w * 0.25f);
        *(float4*)&out[(size_t)node * DD + idx * 4] = o;
        int d0 = idx * 4;
        atomicAdd(&sSum[d0 + 0], o.x); atomicAdd(&sSS[d0 + 0], o.x * o.x);
        atomicAdd(&sSum[d0 + 1], o.y); atomicAdd(&sSS[d0 + 1], o.y * o.y);
        atomicAdd(&sSum[d0 + 2], o.z); atomicAdd(&sSS[d0 + 2], o.z * o.z);
        atomicAdd(&sSum[d0 + 3], o.w); atomicAdd(&sSS[d0 + 3], o.w * o.w);
    }
    __syncthreads();
    if (threadIdx.x < DD) {
        atomicAdd(&g_bnsum[threadIdx.x], sSum[threadIdx.x]);
        atomicAdd(&g_bnss[threadIdx.x],  sSS[threadIdx.x]);
    }
}

// BN apply, float4-vectorized
__global__ void bnapply_kernel(float* __restrict__ out,
                               const float* __restrict__ gamma,
                               const float* __restrict__ beta) {
    int gid = blockIdx.x * blockDim.x + threadIdx.x;     // quad index
    if (gid >= NN * DD / 4) return;
    int d0 = (gid & 15) * 4;
    const float invn = 1.f / (float)NN;
    float4 v = *(float4*)&out[(size_t)gid * 4];
    float4 r;
    {
        float mu = g_bnsum[d0 + 0] * invn;
        float var = g_bnss[d0 + 0] * invn - mu * mu;
        r.x = (v.x - mu) * rsqrtf(var + BN_EPS) * gamma[d0 + 0] + beta[d0 + 0];
        mu = g_bnsum[d0 + 1] * invn;
        var = g_bnss[d0 + 1] * invn - mu * mu;
        r.y = (v.y - mu) * rsqrtf(var + BN_EPS) * gamma[d0 + 1] + beta[d0 + 1];
        mu = g_bnsum[d0 + 2] * invn;
        var = g_bnss[d0 + 2] * invn - mu * mu;
        r.z = (v.z - mu) * rsqrtf(var + BN_EPS) * gamma[d0 + 2] + beta[d0 + 2];
        mu = g_bnsum[d0 + 3] * invn;
        var = g_bnss[d0 + 3] * invn - mu * mu;
        r.w = (v.w - mu) * rsqrtf(var + BN_EPS) * gamma[d0 + 3] + beta[d0 + 3];
    }
    *(float4*)&out[(size_t)gid * 4] = r;
}

// ---------------- launch ----------------
extern "C" void kernel_launch(void* const* d_in, const int* in_sizes, int n_in,
                              void* d_out, int out_size) {
    const float* feats = (const float*)d_in[0];
    const int*   src   = (const int*)d_in[1];
    const int*   dst   = (const int*)d_in[2];
    const float* fcw   = (const float*)d_in[3];
    const float* al    = (const float*)d_in[4];
    const float* ar    = (const float*)d_in[5];
    const float* resw  = (const float*)d_in[6];
    const float* bias  = (const float*)d_in[7];
    const float* gamma = (const float*)d_in[8];
    const float* beta  = (const float*)d_in[9];
    float* out = (float*)d_out;

    // order chosen so the GEMM sits at profiled launch position 4
    zero_kernel<<<(NN + 255) / 256, 256>>>();
    hist_kernel<<<(NE / 4 + 255) / 256, 256>>>(dst);
    scan1_kernel<<<SCAN_B, 1024>>>();
    gemm_bf16_kernel<<<dim3(4, (NN + 127) / 128), 256>>>(feats, fcw, resw, al, ar);
    scan2_kernel<<<1, 128>>>();
    scan3_kernel<<<SCAN_B, 1024>>>();
    scatter_kernel<<<(NE + 255) / 256, 256>>>(src, dst);
    agg_kernel<<<NN / 8, 256>>>(bias, out);
    bnapply_kernel<<<(NN * DD / 4 + 255) / 256, 256>>>(out, gamma, beta);
}

// round 14
// speedup vs baseline: 1.1673x; 1.0704x over previous
#include <cuda_runtime.h>
#include <cuda_fp16.h>
#include <cuda_bf16.h>
#include <cstdint>

// ---------------- problem constants ----------------
namespace {
constexpr int NN   = 100000;
constexpr int NE   = 1600000;
constexpr int NH   = 4;
constexpr int DD   = 64;
constexpr int CIN  = 128;
constexpr int CTOT = 256;
constexpr float NEG_SLOPE = 0.2f;
constexpr float BN_EPS    = 1e-5f;
constexpr int SCAN_B = (NN + 1023) / 1024;
}

// ---------------- scratch ----------------
__device__ __align__(16) __half g_h   [(size_t)NN * CTOT];  // projected feats (fp16)
__device__ __align__(16) __half g_resh[(size_t)NN * CTOT];  // residual proj (fp16)
__device__ __align__(16) float  g_el [NN * NH];
__device__ __align__(16) float  g_er [NN * NH];
__device__ int                  g_cnt[NN];
__device__ int                  g_off[NN + 1];
__device__ int                  g_cur[NN];
__device__ int                  g_ssrc[NE];                 // src sorted by dst
__device__ uint2                g_sexh[NE];                 // ex (4 x fp16) sorted by dst
__device__ float                g_bnsum[DD];
__device__ float                g_bnss [DD];
__device__ int                  g_bsum[128];

// ---------------- helpers ----------------
__device__ __forceinline__ void mma_bf16(float* c, const uint32_t* a,
                                         uint32_t b0, uint32_t b1) {
    asm volatile(
        "mma.sync.aligned.m16n8k16.row.col.f32.bf16.bf16.f32 "
        "{%0,%1,%2,%3},{%4,%5,%6,%7},{%8,%9},{%0,%1,%2,%3};"
        : "+f"(c[0]), "+f"(c[1]), "+f"(c[2]), "+f"(c[3])
        : "r"(a[0]), "r"(a[1]), "r"(a[2]), "r"(a[3]), "r"(b0), "r"(b1));
}
__device__ __forceinline__ void split_pack(float x, float y,
                                           uint32_t& hi, uint32_t& lo) {
    __nv_bfloat16 hx = __float2bfloat16(x);
    __nv_bfloat16 hy = __float2bfloat16(y);
    __nv_bfloat16 lx = __float2bfloat16(x - __bfloat162float(hx));
    __nv_bfloat16 ly = __float2bfloat16(y - __bfloat162float(hy));
    __nv_bfloat162 h2 = __nv_bfloat162(hx, hy);
    __nv_bfloat162 l2 = __nv_bfloat162(lx, ly);
    hi = *(uint32_t*)&h2;
    lo = *(uint32_t*)&l2;
}
__device__ __forceinline__ float elu1(float v) {
    return v > 0.f ? v : (__expf(v) - 1.f);
}
// k2-column interleave: within each 8-block, (q, q+4) -> (2q, 2q+1)
// so fragment pairs ([k],[k+4]) are adjacent -> LDS.64 loads.
__device__ __forceinline__ int nc_map(int k2) {
    return (k2 & 8) | (((k2 & 3) << 1) | ((k2 >> 2) & 1));
}

// ---------------- kernels ----------------

__global__ void zero_kernel() {
    int i = blockIdx.x * blockDim.x + threadIdx.x;
    if (i < NN) g_cnt[i] = 0;
    if (i < DD) { g_bnsum[i] = 0.f; g_bnss[i] = 0.f; }
}

// bf16x3 split tensor-core GEMM + fused el/er epilogue.
// Block 128x128, BK=32, 8 warps (4m x 2n), warp tile 32x64 (= one head wide).
// No register prefetch; __launch_bounds__(256,2) targets 2 CTAs/SM (occ lever).
__global__ __launch_bounds__(256, 2) void gemm_bf16_kernel(
        const float* __restrict__ feats,
        const float* __restrict__ fcw,
        const float* __restrict__ resw,
        const float* __restrict__ al,
        const float* __restrict__ ar) {
    __shared__ __align__(16) uint32_t AsHi[128][20], AsLo[128][20];
    __shared__ __align__(16) uint32_t BsHi[128][20], BsLo[128][20];

    const int tid  = threadIdx.x;
    const int lane = tid & 31;
    const int w    = tid >> 5;
    const int wm   = w & 3;
    const int wn   = w >> 2;
    const int rb   = blockIdx.y * 128;
    const int cb   = blockIdx.x * 128;

    float c[2][8][4];
#pragma unroll
    for (int mt = 0; mt < 2; ++mt)
#pragma unroll
        for (int nt = 0; nt < 8; ++nt)
#pragma unroll
            for (int q = 0; q < 4; ++q) c[mt][nt][q] = 0.f;

    const int qrow = lane >> 2;
    const int qcol = lane & 3;

    // per-thread load coords (fixed across chunks)
    const int lrow = tid >> 3;            // 0..31 base row/col step handled by it
    (void)lrow;

#pragma unroll 1
    for (int chunk = 0; chunk < 4; ++chunk) {
        const int ks = chunk * 32;
#pragma unroll
        for (int it = 0; it < 4; ++it) {
            int i   = it * 256 + tid;
            int row = i >> 3;
            int kq  = (i & 7) * 4;
            int c0  = nc_map(kq / 2);
            int c1  = nc_map(kq / 2 + 1);
            int gr  = rb + row;
            float4 v = make_float4(0.f, 0.f, 0.f, 0.f);
            if (gr < NN) v = *(const float4*)&feats[(size_t)gr * CIN + ks + kq];
            uint32_t h0, l0, h1, l1;
            split_pack(v.x, v.y, h0, l0);
            split_pack(v.z, v.w, h1, l1);
            AsHi[row][c0] = h0; AsLo[row][c0] = l0;
            AsHi[row][c1] = h1; AsLo[row][c1] = l1;
        }
#pragma unroll
        for (int it = 0; it < 4; ++it) {
            int i   = it * 256 + tid;
            int col = i >> 3;
            int kq  = (i & 7) * 4;
            int c0  = nc_map(kq / 2);
            int c1  = nc_map(kq / 2 + 1);
            int gc  = cb + col;
            const float* wp = (gc < CTOT) ? &fcw[(size_t)gc * CIN]
                                          : &resw[(size_t)(gc - CTOT) * CIN];
            float4 v = *(const float4*)&wp[ks + kq];
            uint32_t h0, l0, h1, l1;
            split_pack(v.x, v.y, h0, l0);
            split_pack(v.z, v.w, h1, l1);
            BsHi[col][c0] = h0; BsLo[col][c0] = l0;
            BsHi[col][c1] = h1; BsLo[col][c1] = l1;
        }
        __syncthreads();

#pragma unroll
        for (int k2b = 0; k2b < 16; k2b += 8) {
            const int kc = k2b + 2 * qcol;       // interleaved pair column
            uint32_t aH[2][4], aL[2][4];
#pragma unroll
            for (int mt = 0; mt < 2; ++mt) {
                int rw = wm * 32 + mt * 16 + qrow;
                uint2 vh0 = *(const uint2*)&AsHi[rw][kc];
                uint2 vh1 = *(const uint2*)&AsHi[rw + 8][kc];
                uint2 vl0 = *(const uint2*)&AsLo[rw][kc];
                uint2 vl1 = *(const uint2*)&AsLo[rw + 8][kc];
                aH[mt][0] = vh0.x; aH[mt][2] = vh0.y;
                aH[mt][1] = vh1.x; aH[mt][3] = vh1.y;
                aL[mt][0] = vl0.x; aL[mt][2] = vl0.y;
                aL[mt][1] = vl1.x; aL[mt][3] = vl1.y;
            }
#pragma unroll
            for (int nt = 0; nt < 8; ++nt) {
                int cl = wn * 64 + nt * 8 + qrow;
                uint2 bh = *(const uint2*)&BsHi[cl][kc];
                uint2 bl = *(const uint2*)&BsLo[cl][kc];
#pragma unroll
                for (int mt = 0; mt < 2; ++mt) {
                    mma_bf16(c[mt][nt], aH[mt], bh.x, bh.y);
                    mma_bf16(c[mt][nt], aH[mt], bl.x, bl.y);
                    mma_bf16(c[mt][nt], aL[mt], bh.x, bh.y);
                }
            }
        }
        __syncthreads();
    }

    // epilogue: h -> fp16, res -> fp16
#pragma unroll
    for (int mt = 0; mt < 2; ++mt) {
        int r = rb + wm * 32 + mt * 16 + qrow;
#pragma unroll
        for (int nt = 0; nt < 8; ++nt) {
            int cg = cb + wn * 64 + nt * 8 + qcol * 2;
            __half* base = (cg < CTOT) ? g_h : g_resh;
            int cc = (cg < CTOT) ? cg : cg - CTOT;
            if (r < NN)
                *(__half2*)&base[(size_t)r * CTOT + cc] =
                    __floats2half2_rn(c[mt][nt][0], c[mt][nt][1]);
            if (r + 8 < NN)
                *(__half2*)&base[(size_t)(r + 8) * CTOT + cc] =
                    __floats2half2_rn(c[mt][nt][2], c[mt][nt][3]);
        }
    }

    // fused el/er: warp tile = exactly one head (64 cols)
    if (cb < CTOT) {
        const int head = (cb >> 6) + wn;
#pragma unroll
        for (int mt = 0; mt < 2; ++mt) {
            float pl0 = 0.f, pr0 = 0.f, pl8 = 0.f, pr8 = 0.f;
#pragma unroll
            for (int nt = 0; nt < 8; ++nt) {
                int cg = cb + wn * 64 + nt * 8 + qcol * 2;
                float a0 = al[cg], a1 = al[cg + 1];
                float r0 = ar[cg], r1 = ar[cg + 1];
                pl0 += c[mt][nt][0] * a0 + c[mt][nt][1] * a1;
                pr0 += c[mt][nt][0] * r0 + c[mt][nt][1] * r1;
                pl8 += c[mt][nt][2] * a0 + c[mt][nt][3] * a1;
                pr8 += c[mt][nt][2] * r0 + c[mt][nt][3] * r1;
            }
#pragma unroll
            for (int o = 1; o <= 2; o <<= 1) {
                pl0 += __shfl_xor_sync(0xffffffffu, pl0, o);
                pr0 += __shfl_xor_sync(0xffffffffu, pr0, o);
                pl8 += __shfl_xor_sync(0xffffffffu, pl8, o);
                pr8 += __shfl_xor_sync(0xffffffffu, pr8, o);
            }
            if (qcol == 0) {
                int r = rb + wm * 32 + mt * 16 + qrow;
                if (r < NN)     { g_el[r * NH + head] = pl0; g_er[r * NH + head] = pr0; }
                if (r + 8 < NN) { g_el[(r + 8) * NH + head] = pl8; g_er[(r + 8) * NH + head] = pr8; }
            }
        }
    }
}

// dst histogram (int4-vectorized)
__global__ void hist_kernel(const int* __restrict__ dst) {
    int i = blockIdx.x * blockDim.x + threadIdx.x;
    int i4 = i * 4;
    if (i4 + 3 < NE) {
        int4 d = *(const int4*)&dst[i4];
        atomicAdd(&g_cnt[d.x], 1);
        atomicAdd(&g_cnt[d.y], 1);
        atomicAdd(&g_cnt[d.z], 1);
        atomicAdd(&g_cnt[d.w], 1);
    } else {
        for (int j = i4; j < NE; ++j) atomicAdd(&g_cnt[dst[j]], 1);
    }
}

// 3-kernel exclusive scan of g_cnt -> g_off (+ g_cur copy)
__global__ void scan1_kernel() {
    __shared__ int sd[1024];
    int t = threadIdx.x;
    int gid = blockIdx.x * 1024 + t;
    int v = (gid < NN) ? g_cnt[gid] : 0;
    sd[t] = v; __syncthreads();
    for (int o = 1; o < 1024; o <<= 1) {
        int x = (t >= o) ? sd[t - o] : 0;
        __syncthreads();
        sd[t] += x;
        __syncthreads();
    }
    if (gid < NN) g_off[gid] = sd[t] - v;
    if (t == 1023) g_bsum[blockIdx.x] = sd[1023];
}
__global__ void scan2_kernel() {
    __shared__ int sd[128];
    int t = threadIdx.x;
    int v = (t < SCAN_B) ? g_bsum[t] : 0;
    sd[t] = v; __syncthreads();
    for (int o = 1; o < 128; o <<= 1) {
        int x = (t >= o) ? sd[t - o] : 0;
        __syncthreads();
        sd[t] += x;
        __syncthreads();
    }
    if (t < SCAN_B) g_bsum[t] = sd[t] - v;
}
__global__ void scan3_kernel() {
    int gid = blockIdx.x * 1024 + threadIdx.x;
    if (gid < NN) {
        int o = g_off[gid] + g_bsum[blockIdx.x];
        g_off[gid] = o;
        g_cur[gid] = o;
    }
    if (gid == 0) g_off[NN] = NE;
}

// edge pass: ex = exp(lrelu(el+er)) -> fp16, counting-sort by dst.
__global__ void scatter_kernel(const int* __restrict__ src,
                               const int* __restrict__ dst) {
    int i = blockIdx.x * blockDim.x + threadIdx.x;
    if (i >= NE) return;
    int s = src[i], d = dst[i];
    float4 a = *(const float4*)&g_el[s * NH];
    float4 b = *(const float4*)&g_er[d * NH];
    float t;
    t = a.x + b.x; t = t > 0.f ? t : NEG_SLOPE * t; __half e0 = __float2half(__expf(t));
    t = a.y + b.y; t = t > 0.f ? t : NEG_SLOPE * t; __half e1 = __float2half(__expf(t));
    t = a.z + b.z; t = t > 0.f ? t : NEG_SLOPE * t; __half e2 = __float2half(__expf(t));
    t = a.w + b.w; t = t > 0.f ? t : NEG_SLOPE * t; __half e3 = __float2half(__expf(t));
    int p = atomicAdd(&g_cur[d], 1);
    __half2 p01 = __halves2half2(e0, e1);
    __half2 p23 = __halves2half2(e2, e3);
    g_ssrc[p] = s;
    g_sexh[p] = make_uint2(*(uint32_t*)&p01, *(uint32_t*)&p23);
}

// aggregation + in-register denom + residual + bias + ELU + mean + BN partials.
// One warp/node; thread: 2 heads x 4 d-elems; edge loop unrolled x2.
__global__ __launch_bounds__(256) void agg_kernel(const float* __restrict__ bias,
                                                  float* __restrict__ out) {
    __shared__ float sSum[DD], sSS[DD];
    if (threadIdx.x < DD) { sSum[threadIdx.x] = 0.f; sSS[threadIdx.x] = 0.f; }
    __syncthreads();

    int node = blockIdx.x * 8 + (threadIdx.x >> 5);   // NN % 8 == 0
    int lane = threadIdx.x & 31;
    int grp = lane >> 4;
    int idx = lane & 15;
    int offA = grp * 64 + idx * 4;
    int offB = (grp + 2) * 64 + idx * 4;
    int beg = g_off[node], end = g_off[node + 1];

    float4 accA = make_float4(0.f, 0.f, 0.f, 0.f);
    float4 accB = make_float4(0.f, 0.f, 0.f, 0.f);
    float sA = 0.f, sB = 0.f;

    int e = beg;
#pragma unroll 1
    for (; e + 1 < end; e += 2) {
        int s0 = g_ssrc[e], s1 = g_ssrc[e + 1];
        uint2 w0 = g_sexh[e], w1 = g_sexh[e + 1];
        const __half* hp0 = &g_h[(size_t)s0 * CTOT];
        const __half* hp1 = &g_h[(size_t)s1 * CTOT];
        uint2 ra0 = *(const uint2*)&hp0[offA];
        uint2 rb0 = *(const uint2*)&hp0[offB];
        uint2 ra1 = *(const uint2*)&hp1[offA];
        uint2 rb1 = *(const uint2*)&hp1[offB];
        float wA0 = grp ? __high2float(*(__half2*)&w0.x) : __low2float(*(__half2*)&w0.x);
        float wB0 = grp ? __high2float(*(__half2*)&w0.y) : __low2float(*(__half2*)&w0.y);
        float wA1 = grp ? __high2float(*(__half2*)&w1.x) : __low2float(*(__half2*)&w1.x);
        float wB1 = grp ? __high2float(*(__half2*)&w1.y) : __low2float(*(__half2*)&w1.y);
        sA += wA0 + wA1; sB += wB0 + wB1;
        float2 t0, t1;
        t0 = __half22float2(*(__half2*)&ra0.x); accA.x += wA0 * t0.x; accA.y += wA0 * t0.y;
        t1 = __half22float2(*(__half2*)&ra0.y); accA.z += wA0 * t1.x; accA.w += wA0 * t1.y;
        t0 = __half22float2(*(__half2*)&rb0.x); accB.x += wB0 * t0.x; accB.y += wB0 * t0.y;
        t1 = __half22float2(*(__half2*)&rb0.y); accB.z += wB0 * t1.x; accB.w += wB0 * t1.y;
        t0 = __half22float2(*(__half2*)&ra1.x); accA.x += wA1 * t0.x; accA.y += wA1 * t0.y;
        t1 = __half22float2(*(__half2*)&ra1.y); accA.z += wA1 * t1.x; accA.w += wA1 * t1.y;
        t0 = __half22float2(*(__half2*)&rb1.x); accB.x += wB1 * t0.x; accB.y += wB1 * t0.y;
        t1 = __half22float2(*(__half2*)&rb1.y); accB.z += wB1 * t1.x; accB.w += wB1 * t1.y;
    }
    if (e < end) {
        int s0 = g_ssrc[e];
        uint2 w0 = g_sexh[e];
        const __half* hp0 = &g_h[(size_t)s0 * CTOT];
        uint2 ra0 = *(const uint2*)&hp0[offA];
        uint2 rb0 = *(const uint2*)&hp0[offB];
        float wA0 = grp ? __high2float(*(__half2*)&w0.x) : __low2float(*(__half2*)&w0.x);
        float wB0 = grp ? __high2float(*(__half2*)&w0.y) : __low2float(*(__half2*)&w0.y);
        sA += wA0; sB += wB0;
        float2 t0, t1;
        t0 = __half22float2(*(__half2*)&ra0.x); accA.x += wA0 * t0.x; accA.y += wA0 * t0.y;
        t1 = __half22float2(*(__half2*)&ra0.y); accA.z += wA0 * t1.x; accA.w += wA0 * t1.y;
        t0 = __half22float2(*(__half2*)&rb0.x); accB.x += wB0 * t0.x; accB.y += wB0 * t0.y;
        t1 = __half22float2(*(__half2*)&rb0.y); accB.z += wB0 * t1.x; accB.w += wB0 * t1.y;
    }

    float invA = (sA > 0.f) ? 1.f / sA : 0.f;
    float invB = (sB > 0.f) ? 1.f / sB : 0.f;
    const __half* rp = &g_resh[(size_t)node * CTOT];
    uint2 rAu = *(const uint2*)&rp[offA];
    uint2 rBu = *(const uint2*)&rp[offB];
    float2 rA0 = __half22float2(*(__half2*)&rAu.x);
    float2 rA1 = __half22float2(*(__half2*)&rAu.y);
    float2 rB0 = __half22float2(*(__half2*)&rBu.x);
    float2 rB1 = __half22float2(*(__half2*)&rBu.y);
    float4 bA = *(const float4*)&bias[offA];
    float4 bB = *(const float4*)&bias[offB];
    float4 tot;
    tot.x = elu1(accA.x * invA + rA0.x + bA.x) + elu1(accB.x * invB + rB0.x + bB.x);
    tot.y = elu1(accA.y * invA + rA0.y + bA.y) + elu1(accB.y * invB + rB0.y + bB.y);
    tot.z = elu1(accA.z * invA + rA1.x + bA.z) + elu1(accB.z * invB + rB1.x + bB.z);
    tot.w = elu1(accA.w * invA + rA1.y + bA.w) + elu1(accB.w * invB + rB1.y + bB.w);
    tot.x += __shfl_xor_sync(0xffffffffu, tot.x, 16);
    tot.y += __shfl_xor_sync(0xffffffffu, tot.y, 16);
    tot.z += __shfl_xor_sync(0xffffffffu, tot.z, 16);
    tot.w += __shfl_xor_sync(0xffffffffu, tot.w, 16);
    if (grp == 0) {
        float4 o = make_float4(tot.x * 0.25f, tot.y * 0.25f,
                               tot.z * 0.25f, tot.w * 0.25f);
        *(float4*)&out[(size_t)node * DD + idx * 4] = o;
        int d0 = idx * 4;
        atomicAdd(&sSum[d0 + 0], o.x); atomicAdd(&sSS[d0 + 0], o.x * o.x);
        atomicAdd(&sSum[d0 + 1], o.y); atomicAdd(&sSS[d0 + 1], o.y * o.y);
        atomicAdd(&sSum[d0 + 2], o.z); atomicAdd(&sSS[d0 + 2], o.z * o.z);
        atomicAdd(&sSum[d0 + 3], o.w); atomicAdd(&sSS[d0 + 3], o.w * o.w);
    }
    __syncthreads();
    if (threadIdx.x < DD) {
        atomicAdd(&g_bnsum[threadIdx.x], sSum[threadIdx.x]);
        atomicAdd(&g_bnss[threadIdx.x],  sSS[threadIdx.x]);
    }
}

// BN apply, float4-vectorized
__global__ void bnapply_kernel(float* __restrict__ out,
                               const float* __restrict__ gamma,
                               const float* __restrict__ beta) {
    int gid = blockIdx.x * blockDim.x + threadIdx.x;     // quad index
    if (gid >= NN * DD / 4) return;
    int d0 = (gid & 15) * 4;
    const float invn = 1.f / (float)NN;
    float4 v = *(float4*)&out[(size_t)gid * 4];
    float4 r;
    {
        float mu = g_bnsum[d0 + 0] * invn;
        float var = g_bnss[d0 + 0] * invn - mu * mu;
        r.x = (v.x - mu) * rsqrtf(var + BN_EPS) * gamma[d0 + 0] + beta[d0 + 0];
        mu = g_bnsum[d0 + 1] * invn;
        var = g_bnss[d0 + 1] * invn - mu * mu;
        r.y = (v.y - mu) * rsqrtf(var + BN_EPS) * gamma[d0 + 1] + beta[d0 + 1];
        mu = g_bnsum[d0 + 2] * invn;
        var = g_bnss[d0 + 2] * invn - mu * mu;
        r.z = (v.z - mu) * rsqrtf(var + BN_EPS) * gamma[d0 + 2] + beta[d0 + 2];
        mu = g_bnsum[d0 + 3] * invn;
        var = g_bnss[d0 + 3] * invn - mu * mu;
        r.w = (v.w - mu) * rsqrtf(var + BN_EPS) * gamma[d0 + 3] + beta[d0 + 3];
    }
    *(float4*)&out[(size_t)gid * 4] = r;
}

// ---------------- launch ----------------
extern "C" void kernel_launch(void* const* d_in, const int* in_sizes, int n_in,
                              void* d_out, int out_size) {
    const float* feats = (const float*)d_in[0];
    const int*   src   = (const int*)d_in[1];
    const int*   dst   = (const int*)d_in[2];
    const float* fcw   = (const float*)d_in[3];
    const float* al    = (const float*)d_in[4];
    const float* ar    = (const float*)d_in[5];
    const float* resw  = (const float*)d_in[6];
    const float* bias  = (const float*)d_in[7];
    const float* gamma = (const float*)d_in[8];
    const float* beta  = (const float*)d_in[9];
    float* out = (float*)d_out;

    // order chosen so the GEMM sits at profiled launch position 4
    zero_kernel<<<(NN + 255) / 256, 256>>>();
    hist_kernel<<<(NE / 4 + 255) / 256, 256>>>(dst);
    scan1_kernel<<<SCAN_B, 1024>>>();
    gemm_bf16_kernel<<<dim3(4, (NN + 127) / 128), 256>>>(feats, fcw, resw, al, ar);
    scan2_kernel<<<1, 128>>>();
    scan3_kernel<<<SCAN_B, 1024>>>();
    scatter_kernel<<<(NE + 255) / 256, 256>>>(src, dst);
    agg_kernel<<<NN / 8, 256>>>(bias, out);
    bnapply_kernel<<<(NN * DD / 4 + 255) / 256, 256>>>(out, gamma, beta);
}

// round 15
// speedup vs baseline: 1.1890x; 1.0186x over previous
#include <cuda_runtime.h>
#include <cuda_fp16.h>
#include <cuda_bf16.h>
#include <cstdint>

// ---------------- problem constants ----------------
namespace {
constexpr int NN   = 100000;
constexpr int NE   = 1600000;
constexpr int NH   = 4;
constexpr int DD   = 64;
constexpr int CIN  = 128;
constexpr int CTOT = 256;
constexpr float NEG_SLOPE = 0.2f;
constexpr float BN_EPS    = 1e-5f;
constexpr int SCAN_B = (NN + 1023) / 1024;
// GEMM smem: 4 arrays x 2 bufs x (128 rows x 20 cols) uint32
constexpr int TILE_U32  = 128 * 20;          // 2560
constexpr int BUF_U32   = TILE_U32;          // per array per buf
constexpr int AHI_OFF   = 0;
constexpr int ALO_OFF   = 2 * BUF_U32;       // 5120
constexpr int BHI_OFF   = 4 * BUF_U32;       // 10240
constexpr int BLO_OFF   = 6 * BUF_U32;       // 15360
constexpr int GEMM_SMEM = 8 * BUF_U32 * 4;   // 81920 bytes
}

// ---------------- scratch ----------------
__device__ __align__(16) __half g_h   [(size_t)NN * CTOT];  // projected feats (fp16)
__device__ __align__(16) __half g_resh[(size_t)NN * CTOT];  // residual proj (fp16)
__device__ __align__(16) uint32_t g_aHi[(size_t)NN * 64];   // pre-split A (bf16x2)
__device__ __align__(16) uint32_t g_aLo[(size_t)NN * 64];
__device__ __align__(16) uint32_t g_bHi[512 * 64];          // pre-split weights
__device__ __align__(16) uint32_t g_bLo[512 * 64];
__device__ __align__(16) float  g_el [NN * NH];
__device__ __align__(16) float  g_er [NN * NH];
__device__ int                  g_cnt[NN];
__device__ int                  g_off[NN + 1];
__device__ int                  g_cur[NN];
__device__ int                  g_ssrc[NE];                 // src sorted by dst
__device__ uint2                g_sexh[NE];                 // ex (4 x fp16) sorted by dst
__device__ float                g_bnsum[DD];
__device__ float                g_bnss [DD];
__device__ int                  g_bsum[128];

// ---------------- helpers ----------------
__device__ __forceinline__ void mma_bf16(float* c, const uint32_t* a,
                                         uint32_t b0, uint32_t b1) {
    asm volatile(
        "mma.sync.aligned.m16n8k16.row.col.f32.bf16.bf16.f32 "
        "{%0,%1,%2,%3},{%4,%5,%6,%7},{%8,%9},{%0,%1,%2,%3};"
        : "+f"(c[0]), "+f"(c[1]), "+f"(c[2]), "+f"(c[3])
        : "r"(a[0]), "r"(a[1]), "r"(a[2]), "r"(a[3]), "r"(b0), "r"(b1));
}
__device__ __forceinline__ void split_pack(float x, float y,
                                           uint32_t& hi, uint32_t& lo) {
    __nv_bfloat16 hx = __float2bfloat16(x);
    __nv_bfloat16 hy = __float2bfloat16(y);
    __nv_bfloat16 lx = __float2bfloat16(x - __bfloat162float(hx));
    __nv_bfloat16 ly = __float2bfloat16(y - __bfloat162float(hy));
    __nv_bfloat162 h2 = __nv_bfloat162(hx, hy);
    __nv_bfloat162 l2 = __nv_bfloat162(lx, ly);
    hi = *(uint32_t*)&h2;
    lo = *(uint32_t*)&l2;
}
__device__ __forceinline__ float elu1(float v) {
    return v > 0.f ? v : (__expf(v) - 1.f);
}
// k2-column interleave: within each 8-block, (q, q+4) -> (2q, 2q+1)
__device__ __forceinline__ int nc_map(int k2) {
    return (k2 & 8) | (((k2 & 3) << 1) | ((k2 >> 2) & 1));
}
__device__ __forceinline__ void cp16(uint32_t* dst, const uint32_t* src) {
    uint32_t d;
    asm("{ .reg .u64 t; cvta.to.shared.u64 t, %1; cvt.u32.u64 %0, t; }"
        : "=r"(d) : "l"(dst));
    asm volatile("cp.async.ca.shared.global [%0], [%1], 16;"
                 :: "r"(d), "l"(src));
}

// ---------------- kernels ----------------

__global__ void zero_kernel() {
    int i = blockIdx.x * blockDim.x + threadIdx.x;
    if (i < NN) g_cnt[i] = 0;
    if (i < DD) { g_bnsum[i] = 0.f; g_bnss[i] = 0.f; }
}

// pre-split feats into bf16 hi/lo, tile-interleaved layout
__global__ void prep_a_kernel(const float* __restrict__ feats) {
    int i = blockIdx.x * blockDim.x + threadIdx.x;   // pair index
    if (i >= NN * 64) return;
    int row = i >> 6, p = i & 63;
    float2 v = *(const float2*)&feats[(size_t)row * CIN + p * 2];
    uint32_t hi, lo;
    split_pack(v.x, v.y, hi, lo);
    int col = (p & ~15) + nc_map(p & 15);
    g_aHi[(size_t)row * 64 + col] = hi;
    g_aLo[(size_t)row * 64 + col] = lo;
}

// pre-split weights (rows 0-255 fc_w, 256-511 res_w)
__global__ void prep_b_kernel(const float* __restrict__ fcw,
                              const float* __restrict__ resw) {
    int i = blockIdx.x * blockDim.x + threadIdx.x;
    if (i >= 512 * 64) return;
    int row = i >> 6, p = i & 63;
    const float* wp = (row < CTOT) ? &fcw[(size_t)row * CIN]
                                   : &resw[(size_t)(row - CTOT) * CIN];
    float2 v = *(const float2*)&wp[p * 2];
    uint32_t hi, lo;
    split_pack(v.x, v.y, hi, lo);
    int col = (p & ~15) + nc_map(p & 15);
    g_bHi[row * 64 + col] = hi;
    g_bLo[row * 64 + col] = lo;
}

// bf16x3 split tensor-core GEMM, cp.async double-buffered, fused el/er epilogue.
// Block 128x128, BK=32, 8 warps (4m x 2n), warp tile 32x64 (= one head wide).
__global__ __launch_bounds__(256, 2) void gemm_bf16_kernel(
        const float* __restrict__ al,
        const float* __restrict__ ar) {
    extern __shared__ __align__(16) uint32_t smem[];
    const int tid  = threadIdx.x;
    const int lane = tid & 31;
    const int w    = tid >> 5;
    const int wm   = w & 3;
    const int wn   = w >> 2;
    const int rb   = blockIdx.y * 128;
    const int cb   = blockIdx.x * 128;

    float c[2][8][4];
#pragma unroll
    for (int mt = 0; mt < 2; ++mt)
#pragma unroll
        for (int nt = 0; nt < 8; ++nt)
#pragma unroll
            for (int q = 0; q < 4; ++q) c[mt][nt][q] = 0.f;

    const int qrow = lane >> 2;
    const int qcol = lane & 3;

    // per-thread copy coords: i in [0,512): row = i>>2, c4 = (i&3)*4
    const int r0 = (tid) >> 2;            // it=0 row
    const int r1 = (256 + tid) >> 2;      // it=1 row
    const int c40 = (tid & 3) * 4;
    int gra0 = rb + r0; if (gra0 >= NN) gra0 = NN - 1;
    int gra1 = rb + r1; if (gra1 >= NN) gra1 = NN - 1;
    const int gc0 = cb + r0, gc1 = cb + r1;

    // issue copies for one chunk into buffer buf
    auto issue = [&](int chunk, int buf) {
        int base = buf * BUF_U32;
        int kofs = chunk * 16 + c40;
        cp16(&smem[AHI_OFF + base + r0 * 20 + c40], &g_aHi[(size_t)gra0 * 64 + kofs]);
        cp16(&smem[AHI_OFF + base + r1 * 20 + c40], &g_aHi[(size_t)gra1 * 64 + kofs]);
        cp16(&smem[ALO_OFF + base + r0 * 20 + c40], &g_aLo[(size_t)gra0 * 64 + kofs]);
        cp16(&smem[ALO_OFF + base + r1 * 20 + c40], &g_aLo[(size_t)gra1 * 64 + kofs]);
        cp16(&smem[BHI_OFF + base + r0 * 20 + c40], &g_bHi[(size_t)gc0 * 64 + kofs]);
        cp16(&smem[BHI_OFF + base + r1 * 20 + c40], &g_bHi[(size_t)gc1 * 64 + kofs]);
        cp16(&smem[BLO_OFF + base + r0 * 20 + c40], &g_bLo[(size_t)gc0 * 64 + kofs]);
        cp16(&smem[BLO_OFF + base + r1 * 20 + c40], &g_bLo[(size_t)gc1 * 64 + kofs]);
        asm volatile("cp.async.commit_group;");
    };

    issue(0, 0);
#pragma unroll
    for (int chunk = 0; chunk < 4; ++chunk) {
        if (chunk < 3) {
            issue(chunk + 1, (chunk + 1) & 1);
            asm volatile("cp.async.wait_group 1;");
        } else {
            asm volatile("cp.async.wait_group 0;");
        }
        __syncthreads();

        const int base = (chunk & 1) * BUF_U32;
#pragma unroll
        for (int k2b = 0; k2b < 16; k2b += 8) {
            const int kc = k2b + 2 * qcol;
            uint32_t aH[2][4], aL[2][4];
#pragma unroll
            for (int mt = 0; mt < 2; ++mt) {
                int rw = wm * 32 + mt * 16 + qrow;
                uint2 vh0 = *(const uint2*)&smem[AHI_OFF + base + rw * 20 + kc];
                uint2 vh1 = *(const uint2*)&smem[AHI_OFF + base + (rw + 8) * 20 + kc];
                uint2 vl0 = *(const uint2*)&smem[ALO_OFF + base + rw * 20 + kc];
                uint2 vl1 = *(const uint2*)&smem[ALO_OFF + base + (rw + 8) * 20 + kc];
                aH[mt][0] = vh0.x; aH[mt][2] = vh0.y;
                aH[mt][1] = vh1.x; aH[mt][3] = vh1.y;
                aL[mt][0] = vl0.x; aL[mt][2] = vl0.y;
                aL[mt][1] = vl1.x; aL[mt][3] = vl1.y;
            }
#pragma unroll
            for (int nt = 0; nt < 8; ++nt) {
                int cl = wn * 64 + nt * 8 + qrow;
                uint2 bh = *(const uint2*)&smem[BHI_OFF + base + cl * 20 + kc];
                uint2 bl = *(const uint2*)&smem[BLO_OFF + base + cl * 20 + kc];
#pragma unroll
                for (int mt = 0; mt < 2; ++mt) {
                    mma_bf16(c[mt][nt], aH[mt], bh.x, bh.y);
                    mma_bf16(c[mt][nt], aH[mt], bl.x, bl.y);
                    mma_bf16(c[mt][nt], aL[mt], bh.x, bh.y);
                }
            }
        }
        __syncthreads();
    }

    // epilogue: h -> fp16, res -> fp16
#pragma unroll
    for (int mt = 0; mt < 2; ++mt) {
        int r = rb + wm * 32 + mt * 16 + qrow;
#pragma unroll
        for (int nt = 0; nt < 8; ++nt) {
            int cg = cb + wn * 64 + nt * 8 + qcol * 2;
            __half* base = (cg < CTOT) ? g_h : g_resh;
            int cc = (cg < CTOT) ? cg : cg - CTOT;
            if (r < NN)
                *(__half2*)&base[(size_t)r * CTOT + cc] =
                    __floats2half2_rn(c[mt][nt][0], c[mt][nt][1]);
            if (r + 8 < NN)
                *(__half2*)&base[(size_t)(r + 8) * CTOT + cc] =
                    __floats2half2_rn(c[mt][nt][2], c[mt][nt][3]);
        }
    }

    // fused el/er: warp tile = exactly one head (64 cols)
    if (cb < CTOT) {
        const int head = (cb >> 6) + wn;
#pragma unroll
        for (int mt = 0; mt < 2; ++mt) {
            float pl0 = 0.f, pr0 = 0.f, pl8 = 0.f, pr8 = 0.f;
#pragma unroll
            for (int nt = 0; nt < 8; ++nt) {
                int cg = cb + wn * 64 + nt * 8 + qcol * 2;
                float a0 = al[cg], a1 = al[cg + 1];
                float rr0 = ar[cg], rr1 = ar[cg + 1];
                pl0 += c[mt][nt][0] * a0 + c[mt][nt][1] * a1;
                pr0 += c[mt][nt][0] * rr0 + c[mt][nt][1] * rr1;
                pl8 += c[mt][nt][2] * a0 + c[mt][nt][3] * a1;
                pr8 += c[mt][nt][2] * rr0 + c[mt][nt][3] * rr1;
            }
#pragma unroll
            for (int o = 1; o <= 2; o <<= 1) {
                pl0 += __shfl_xor_sync(0xffffffffu, pl0, o);
                pr0 += __shfl_xor_sync(0xffffffffu, pr0, o);
                pl8 += __shfl_xor_sync(0xffffffffu, pl8, o);
                pr8 += __shfl_xor_sync(0xffffffffu, pr8, o);
            }
            if (qcol == 0) {
                int r = rb + wm * 32 + mt * 16 + qrow;
                if (r < NN)     { g_el[r * NH + head] = pl0; g_er[r * NH + head] = pr0; }
                if (r + 8 < NN) { g_el[(r + 8) * NH + head] = pl8; g_er[(r + 8) * NH + head] = pr8; }
            }
        }
    }
}

// dst histogram (int4-vectorized)
__global__ void hist_kernel(const int* __restrict__ dst) {
    int i = blockIdx.x * blockDim.x + threadIdx.x;
    int i4 = i * 4;
    if (i4 + 3 < NE) {
        int4 d = *(const int4*)&dst[i4];
        atomicAdd(&g_cnt[d.x], 1);
        atomicAdd(&g_cnt[d.y], 1);
        atomicAdd(&g_cnt[d.z], 1);
        atomicAdd(&g_cnt[d.w], 1);
    } else {
        for (int j = i4; j < NE; ++j) atomicAdd(&g_cnt[dst[j]], 1);
    }
}

// 3-kernel exclusive scan of g_cnt -> g_off (+ g_cur copy)
__global__ void scan1_kernel() {
    __shared__ int sd[1024];
    int t = threadIdx.x;
    int gid = blockIdx.x * 1024 + t;
    int v = (gid < NN) ? g_cnt[gid] : 0;
    sd[t] = v; __syncthreads();
    for (int o = 1; o < 1024; o <<= 1) {
        int x = (t >= o) ? sd[t - o] : 0;
        __syncthreads();
        sd[t] += x;
        __syncthreads();
    }
    if (gid < NN) g_off[gid] = sd[t] - v;
    if (t == 1023) g_bsum[blockIdx.x] = sd[1023];
}
__global__ void scan2_kernel() {
    __shared__ int sd[128];
    int t = threadIdx.x;
    int v = (t < SCAN_B) ? g_bsum[t] : 0;
    sd[t] = v; __syncthreads();
    for (int o = 1; o < 128; o <<= 1) {
        int x = (t >= o) ? sd[t - o] : 0;
        __syncthreads();
        sd[t] += x;
        __syncthreads();
    }
    if (t < SCAN_B) g_bsum[t] = sd[t] - v;
}
__global__ void scan3_kernel() {
    int gid = blockIdx.x * 1024 + threadIdx.x;
    if (gid < NN) {
        int o = g_off[gid] + g_bsum[blockIdx.x];
        g_off[gid] = o;
        g_cur[gid] = o;
    }
    if (gid == 0) g_off[NN] = NE;
}

// edge pass: ex = exp(lrelu(el+er)) -> fp16, counting-sort by dst.
__global__ void scatter_kernel(const int* __restrict__ src,
                               const int* __restrict__ dst) {
    int i = blockIdx.x * blockDim.x + threadIdx.x;
    if (i >= NE) return;
    int s = src[i], d = dst[i];
    float4 a = *(const float4*)&g_el[s * NH];
    float4 b = *(const float4*)&g_er[d * NH];
    float t;
    t = a.x + b.x; t = t > 0.f ? t : NEG_SLOPE * t; __half e0 = __float2half(__expf(t));
    t = a.y + b.y; t = t > 0.f ? t : NEG_SLOPE * t; __half e1 = __float2half(__expf(t));
    t = a.z + b.z; t = t > 0.f ? t : NEG_SLOPE * t; __half e2 = __float2half(__expf(t));
    t = a.w + b.w; t = t > 0.f ? t : NEG_SLOPE * t; __half e3 = __float2half(__expf(t));
    int p = atomicAdd(&g_cur[d], 1);
    __half2 p01 = __halves2half2(e0, e1);
    __half2 p23 = __halves2half2(e2, e3);
    g_ssrc[p] = s;
    g_sexh[p] = make_uint2(*(uint32_t*)&p01, *(uint32_t*)&p23);
}

// aggregation + in-register denom + residual + bias + ELU + mean + BN partials.
__global__ __launch_bounds__(256) void agg_kernel(const float* __restrict__ bias,
                                                  float* __restrict__ out) {
    __shared__ float sSum[DD], sSS[DD];
    if (threadIdx.x < DD) { sSum[threadIdx.x] = 0.f; sSS[threadIdx.x] = 0.f; }
    __syncthreads();

    int node = blockIdx.x * 8 + (threadIdx.x >> 5);   // NN % 8 == 0
    int lane = threadIdx.x & 31;
    int grp = lane >> 4;
    int idx = lane & 15;
    int offA = grp * 64 + idx * 4;
    int offB = (grp + 2) * 64 + idx * 4;
    int beg = g_off[node], end = g_off[node + 1];

    float4 accA = make_float4(0.f, 0.f, 0.f, 0.f);
    float4 accB = make_float4(0.f, 0.f, 0.f, 0.f);
    float sA = 0.f, sB = 0.f;

    int e = beg;
#pragma unroll 1
    for (; e + 1 < end; e += 2) {
        int s0 = g_ssrc[e], s1 = g_ssrc[e + 1];
        uint2 w0 = g_sexh[e], w1 = g_sexh[e + 1];
        const __half* hp0 = &g_h[(size_t)s0 * CTOT];
        const __half* hp1 = &g_h[(size_t)s1 * CTOT];
        uint2 ra0 = *(const uint2*)&hp0[offA];
        uint2 rb0 = *(const uint2*)&hp0[offB];
        uint2 ra1 = *(const uint2*)&hp1[offA];
        uint2 rb1 = *(const uint2*)&hp1[offB];
        float wA0 = grp ? __high2float(*(__half2*)&w0.x) : __low2float(*(__half2*)&w0.x);
        float wB0 = grp ? __high2float(*(__half2*)&w0.y) : __low2float(*(__half2*)&w0.y);
        float wA1 = grp ? __high2float(*(__half2*)&w1.x) : __low2float(*(__half2*)&w1.x);
        float wB1 = grp ? __high2float(*(__half2*)&w1.y) : __low2float(*(__half2*)&w1.y);
        sA += wA0 + wA1; sB += wB0 + wB1;
        float2 t0, t1;
        t0 = __half22float2(*(__half2*)&ra0.x); accA.x += wA0 * t0.x; accA.y += wA0 * t0.y;
        t1 = __half22float2(*(__half2*)&ra0.y); accA.z += wA0 * t1.x; accA.w += wA0 * t1.y;
        t0 = __half22float2(*(__half2*)&rb0.x); accB.x += wB0 * t0.x; accB.y += wB0 * t0.y;
        t1 = __half22float2(*(__half2*)&rb0.y); accB.z += wB0 * t1.x; accB.w += wB0 * t1.y;
        t0 = __half22float2(*(__half2*)&ra1.x); accA.x += wA1 * t0.x; accA.y += wA1 * t0.y;
        t1 = __half22float2(*(__half2*)&ra1.y); accA.z += wA1 * t1.x; accA.w += wA1 * t1.y;
        t0 = __half22float2(*(__half2*)&rb1.x); accB.x += wB1 * t0.x; accB.y += wB1 * t0.y;
        t1 = __half22float2(*(__half2*)&rb1.y); accB.z += wB1 * t1.x; accB.w += wB1 * t1.y;
    }
    if (e < end) {
        int s0 = g_ssrc[e];
        uint2 w0 = g_sexh[e];
        const __half* hp0 = &g_h[(size_t)s0 * CTOT];
        uint2 ra0 = *(const uint2*)&hp0[offA];
        uint2 rb0 = *(const uint2*)&hp0[offB];
        float wA0 = grp ? __high2float(*(__half2*)&w0.x) : __low2float(*(__half2*)&w0.x);
        float wB0 = grp ? __high2float(*(__half2*)&w0.y) : __low2float(*(__half2*)&w0.y);
        sA += wA0; sB += wB0;
        float2 t0, t1;
        t0 = __half22float2(*(__half2*)&ra0.x); accA.x += wA0 * t0.x; accA.y += wA0 * t0.y;
        t1 = __half22float2(*(__half2*)&ra0.y); accA.z += wA0 * t1.x; accA.w += wA0 * t1.y;
        t0 = __half22float2(*(__half2*)&rb0.x); accB.x += wB0 * t0.x; accB.y += wB0 * t0.y;
        t1 = __half22float2(*(__half2*)&rb0.y); accB.z += wB0 * t1.x; accB.w += wB0 * t1.y;
    }

    float invA = (sA > 0.f) ? 1.f / sA : 0.f;
    float invB = (sB > 0.f) ? 1.f / sB : 0.f;
    const __half* rp = &g_resh[(size_t)node * CTOT];
    uint2 rAu = *(const uint2*)&rp[offA];
    uint2 rBu = *(const uint2*)&rp[offB];
    float2 rA0 = __half22float2(*(__half2*)&rAu.x);
    float2 rA1 = __half22float2(*(__half2*)&rAu.y);
    float2 rB0 = __half22float2(*(__half2*)&rBu.x);
    float2 rB1 = __half22float2(*(__half2*)&rBu.y);
    float4 bA = *(const float4*)&bias[offA];
    float4 bB = *(const float4*)&bias[offB];
    float4 tot;
    tot.x = elu1(accA.x * invA + rA0.x + bA.x) + elu1(accB.x * invB + rB0.x + bB.x);
    tot.y = elu1(accA.y * invA + rA0.y + bA.y) + elu1(accB.y * invB + rB0.y + bB.y);
    tot.z = elu1(accA.z * invA + rA1.x + bA.z) + elu1(accB.z * invB + rB1.x + bB.z);
    tot.w = elu1(accA.w * invA + rA1.y + bA.w) + elu1(accB.w * invB + rB1.y + bB.w);
    tot.x += __shfl_xor_sync(0xffffffffu, tot.x, 16);
    tot.y += __shfl_xor_sync(0xffffffffu, tot.y, 16);
    tot.z += __shfl_xor_sync(0xffffffffu, tot.z, 16);
    tot.w += __shfl_xor_sync(0xffffffffu, tot.w, 16);
    if (grp == 0) {
        float4 o = make_float4(tot.x * 0.25f, tot.y * 0.25f,
                               tot.z * 0.25f, tot.w * 0.25f);
        *(float4*)&out[(size_t)node * DD + idx * 4] = o;
        int d0 = idx * 4;
        atomicAdd(&sSum[d0 + 0], o.x); atomicAdd(&sSS[d0 + 0], o.x * o.x);
        atomicAdd(&sSum[d0 + 1], o.y); atomicAdd(&sSS[d0 + 1], o.y * o.y);
        atomicAdd(&sSum[d0 + 2], o.z); atomicAdd(&sSS[d0 + 2], o.z * o.z);
        atomicAdd(&sSum[d0 + 3], o.w); atomicAdd(&sSS[d0 + 3], o.w * o.w);
    }
    __syncthreads();
    if (threadIdx.x < DD) {
        atomicAdd(&g_bnsum[threadIdx.x], sSum[threadIdx.x]);
        atomicAdd(&g_bnss[threadIdx.x],  sSS[threadIdx.x]);
    }
}

// BN apply, float4-vectorized
__global__ void bnapply_kernel(float* __restrict__ out,
                               const float* __restrict__ gamma,
                               const float* __restrict__ beta) {
    int gid = blockIdx.x * blockDim.x + threadIdx.x;     // quad index
    if (gid >= NN * DD / 4) return;
    int d0 = (gid & 15) * 4;
    const float invn = 1.f / (float)NN;
    float4 v = *(float4*)&out[(size_t)gid * 4];
    float4 r;
    {
        float mu = g_bnsum[d0 + 0] * invn;
        float var = g_bnss[d0 + 0] * invn - mu * mu;
        r.x = (v.x - mu) * rsqrtf(var + BN_EPS) * gamma[d0 + 0] + beta[d0 + 0];
        mu = g_bnsum[d0 + 1] * invn;
        var = g_bnss[d0 + 1] * invn - mu * mu;
        r.y = (v.y - mu) * rsqrtf(var + BN_EPS) * gamma[d0 + 1] + beta[d0 + 1];
        mu = g_bnsum[d0 + 2] * invn;
        var = g_bnss[d0 + 2] * invn - mu * mu;
        r.z = (v.z - mu) * rsqrtf(var + BN_EPS) * gamma[d0 + 2] + beta[d0 + 2];
        mu = g_bnsum[d0 + 3] * invn;
        var = g_bnss[d0 + 3] * invn - mu * mu;
        r.w = (v.w - mu) * rsqrtf(var + BN_EPS) * gamma[d0 + 3] + beta[d0 + 3];
    }
    *(float4*)&out[(size_t)gid * 4] = r;
}

// ---------------- launch ----------------
extern "C" void kernel_launch(void* const* d_in, const int* in_sizes, int n_in,
                              void* d_out, int out_size) {
    const float* feats = (const float*)d_in[0];
    const int*   src   = (const int*)d_in[1];
    const int*   dst   = (const int*)d_in[2];
    const float* fcw   = (const float*)d_in[3];
    const float* al    = (const float*)d_in[4];
    const float* ar    = (const float*)d_in[5];
    const float* resw  = (const float*)d_in[6];
    const float* bias  = (const float*)d_in[7];
    const float* gamma = (const float*)d_in[8];
    const float* beta  = (const float*)d_in[9];
    float* out = (float*)d_out;

    static bool attr_set = false;
    if (!attr_set) {
        cudaFuncSetAttribute(gemm_bf16_kernel,
                             cudaFuncAttributeMaxDynamicSharedMemorySize, GEMM_SMEM);
        attr_set = true;
    }

    // order: gemm at profiled launch position 4
    zero_kernel<<<(NN + 255) / 256, 256>>>();
    prep_a_kernel<<<(NN * 64 + 255) / 256, 256>>>(feats);
    prep_b_kernel<<<(512 * 64 + 255) / 256, 256>>>(fcw, resw);
    gemm_bf16_kernel<<<dim3(4, (NN + 127) / 128), 256, GEMM_SMEM>>>(al, ar);
    hist_kernel<<<(NE / 4 + 255) / 256, 256>>>(dst);
    scan1_kernel<<<SCAN_B, 1024>>>();
    scan2_kernel<<<1, 128>>>();
    scan3_kernel<<<SCAN_B, 1024>>>();
    scatter_kernel<<<(NE + 255) / 256, 256>>>(src, dst);
    agg_kernel<<<NN / 8, 256>>>(bias, out);
    bnapply_kernel<<<(NN * DD / 4 + 255) / 256, 256>>>(out, gamma, beta);
}